// round 15
// baseline (speedup 1.0000x reference)
#include <cuda_runtime.h>
#include <cuda_fp16.h>
#include <cstdint>
#include <math.h>

#define B_ 4
#define N_ 4096
#define C_ 768
#define H_ 12
#define D_ 64
#define BH_ 48
#define M_ (B_*N_)
#define EPS_ 1e-6f

// ---- mma.sync GEMM config (R12/R14 best) ----
#define KDIM 768
#define KCHUNK 64
#define NCHUNKS 12
#define ROWH 72
#define ROWB (ROWH*2)
#define TILE_BYTES (128*ROWB)
#define STAGE_BYTES (2*TILE_BYTES)
#define GEMM_SMEM (3*STAGE_BYTES)    // 110592

// ---- fused flow kernel ----
#define FLOW_Y 8
#define FLOW_GRID (BH_*FLOW_Y)       // 384 blocks
#define FLOW_ROWS (N_/FLOW_Y)        // 512 rows/block

// ---------------- scratch ----------------
__device__ float g_qh[BH_*N_*D_];
__device__ float g_kh[BH_*N_*D_];
__device__ float g_vh[BH_*N_*D_];
__device__ float g_mh[BH_*N_*D_];
__device__ float g_msum[BH_*D_];
__device__ float g_qesum[BH_*D_];
__device__ float g_kesum[BH_*D_];
__device__ float g_qhsum[BH_*D_];
__device__ float g_khsum[BH_*D_];
__device__ float g_qsisum[BH_*D_];
__device__ float g_ksosum[BH_*D_];
__device__ float g_si[BH_*N_];
__device__ float g_ssink[BH_*N_];
__device__ float g_sumexp[BH_];
__device__ float g_agg[BH_*D_*D_];
__device__ unsigned g_flowbar;
__device__ __half g_ah[(size_t)3*M_*C_];
__device__ __half g_wh[(size_t)5*C_*C_];

__device__ __forceinline__ float sigm(float x) { return 1.f / (1.f + __expf(-x)); }

__device__ __forceinline__ uint32_t smem_u32(const void* p) {
    uint32_t a;
    asm("{ .reg .u64 t; cvta.to.shared.u64 t, %1; cvt.u32.u64 %0, t; }" : "=r"(a) : "l"(p));
    return a;
}
__device__ __forceinline__ void cpasync16(uint32_t dst, const void* src) {
    asm volatile("cp.async.cg.shared.global [%0], [%1], 16;" :: "r"(dst), "l"(src) : "memory");
}
#define LDSM4(r0,r1,r2,r3,addr) \
    asm volatile("ldmatrix.sync.aligned.m8n8.x4.shared.b16 {%0,%1,%2,%3}, [%4];" \
        : "=r"(r0),"=r"(r1),"=r"(r2),"=r"(r3) : "r"(addr))
#define MMA16816(c, a, b0, b1) \
    asm volatile("mma.sync.aligned.m16n8k16.row.col.f32.f16.f16.f32 " \
        "{%0,%1,%2,%3}, {%4,%5,%6,%7}, {%8,%9}, {%0,%1,%2,%3};" \
        : "+f"((c)[0]),"+f"((c)[1]),"+f"((c)[2]),"+f"((c)[3]) \
        : "r"((a)[0]),"r"((a)[1]),"r"((a)[2]),"r"((a)[3]),"r"(b0),"r"(b1))

// ---------------- zero accumulators + barrier counter ----------------
__global__ void zero_kernel() {
    int i = blockIdx.x * blockDim.x + threadIdx.x;
    if (i < BH_*D_) {
        g_msum[i] = 0.f; g_qesum[i] = 0.f; g_kesum[i] = 0.f;
        g_qhsum[i] = 0.f; g_khsum[i] = 0.f; g_qsisum[i] = 0.f; g_ksosum[i] = 0.f;
    }
    if (i < BH_) g_sumexp[i] = 0.f;
    if (i == 0) g_flowbar = 0u;
    if (i < BH_*D_*D_) g_agg[i] = 0.f;
}

// ---------------- fp32 -> fp16 ----------------
__global__ void f2h_acts_kernel(const float* a0, const float* a1, const float* a2,
                                __half* __restrict__ dst) {
    const int n4 = M_ * C_ / 4;
    int i = blockIdx.x * 256 + threadIdx.x;
    if (i >= n4) return;
    const float* src = blockIdx.y == 0 ? a0 : blockIdx.y == 1 ? a1 : a2;
    float4 v = ((const float4*)src)[i];
    __half* d = dst + (size_t)blockIdx.y * M_ * C_;
    ((__half2*)d)[i*2]   = __floats2half2_rn(v.x, v.y);
    ((__half2*)d)[i*2+1] = __floats2half2_rn(v.z, v.w);
}
__global__ void f2h_w5_kernel(const float* w0, const float* w1, const float* w2,
                              const float* w3, const float* w4, __half* __restrict__ dst) {
    const int n4 = C_ * C_ / 4;
    int i = blockIdx.x * 256 + threadIdx.x;
    if (i >= n4) return;
    const float* src = blockIdx.y == 0 ? w0 : blockIdx.y == 1 ? w1 : blockIdx.y == 2 ? w2
                     : blockIdx.y == 3 ? w3 : w4;
    float4 v = ((const float4*)src)[i];
    __half* d = dst + (size_t)blockIdx.y * C_ * C_;
    ((__half2*)d)[i*2]   = __floats2half2_rn(v.x, v.y);
    ((__half2*)d)[i*2+1] = __floats2half2_rn(v.z, v.w);
}

// ---------------- GEMM mainloop (R12/R14) ----------------
template<typename LoaderT>
__device__ __forceinline__ void gemm_mainloop(
    float c[2][8][4], const uint32_t sbase, const int tid, const int lane,
    const int wm, const int wn, LoaderT load_stage) {
    const int lrow = lane & 15;
    const int lkof = (lane >> 4) * 8;
    const uint32_t rowOffA = (wm * 32 + lrow) * ROWB;

    uint32_t af[2][8], bf[2][16];

    for (int kt = 0; kt < NCHUNKS; kt++) {
        if (kt + 1 < NCHUNKS) asm volatile("cp.async.wait_group 1;" ::: "memory");
        else                  asm volatile("cp.async.wait_group 0;" ::: "memory");
        __syncthreads();
        const int s = kt % 3;
        const uint32_t aBase = sbase + s * STAGE_BYTES;
        const uint32_t bBase = aBase + TILE_BYTES;
        if (kt + 2 < NCHUNKS) load_stage((kt + 2) % 3, kt + 2);

        {
            const uint32_t kb = lkof * 2;
            const uint32_t aA = aBase + rowOffA + kb;
            LDSM4(af[0][0], af[0][1], af[0][2], af[0][3], aA);
            LDSM4(af[0][4], af[0][5], af[0][6], af[0][7], aA + 16 * ROWB);
            #pragma unroll
            for (int nb = 0; nb < 4; nb++) {
                const uint32_t aB = bBase + (wn * 64 + nb * 16 + lrow) * ROWB + kb;
                LDSM4(bf[0][nb*4+0], bf[0][nb*4+1], bf[0][nb*4+2], bf[0][nb*4+3], aB);
            }
        }
        #pragma unroll
        for (int ks = 0; ks < 4; ks++) {
            const int cur = ks & 1, nxt = cur ^ 1;
            if (ks < 3) {
                const uint32_t kb = ((ks + 1) * 16 + lkof) * 2;
                const uint32_t aA = aBase + rowOffA + kb;
                LDSM4(af[nxt][0], af[nxt][1], af[nxt][2], af[nxt][3], aA);
                LDSM4(af[nxt][4], af[nxt][5], af[nxt][6], af[nxt][7], aA + 16 * ROWB);
                #pragma unroll
                for (int nb = 0; nb < 4; nb++) {
                    const uint32_t aB = bBase + (wn * 64 + nb * 16 + lrow) * ROWB + kb;
                    LDSM4(bf[nxt][nb*4+0], bf[nxt][nb*4+1], bf[nxt][nb*4+2], bf[nxt][nb*4+3], aB);
                }
            }
            #pragma unroll
            for (int nb = 0; nb < 4; nb++) {
                MMA16816(c[0][2*nb],   af[cur],     bf[cur][nb*4+0], bf[cur][nb*4+2]);
                MMA16816(c[1][2*nb],   af[cur] + 4, bf[cur][nb*4+0], bf[cur][nb*4+2]);
                MMA16816(c[0][2*nb+1], af[cur],     bf[cur][nb*4+1], bf[cur][nb*4+3]);
                MMA16816(c[1][2*nb+1], af[cur] + 4, bf[cur][nb*4+1], bf[cur][nb*4+3]);
            }
        }
    }
}

// ---------------- merged projection GEMM ----------------
__global__ void __launch_bounds__(256, 2)
gemm_proj(const __half* __restrict__ Aall, const __half* __restrict__ Wall,
          const float* __restrict__ bq, const float* __restrict__ bk,
          const float* __restrict__ bv, const float* __restrict__ bm,
          float* __restrict__ oq, float* __restrict__ ok,
          float* __restrict__ ov, float* __restrict__ om) {
    extern __shared__ char smem[];
    const uint32_t sbase = smem_u32(smem);
    const int tid = threadIdx.x;
    const int lane = tid & 31, w = tid >> 5;
    const int wm = w & 3, wn = w >> 2;
    const int z = blockIdx.z;
    const int rowBase = blockIdx.y * 128, colBase = blockIdx.x * 128;
    const int aslot = (z == 0) ? 0 : (z == 3) ? 2 : 1;
    const __half* Ab = Aall + (size_t)aslot * M_ * C_ + (size_t)rowBase * KDIM;
    const __half* Wb = Wall + (size_t)z * C_ * C_ + (size_t)colBase * KDIM;
    const float* bias = (z == 0) ? bq : (z == 1) ? bk : (z == 2) ? bv : bm;
    float* out = (z == 0) ? oq : (z == 1) ? ok : (z == 2) ? ov : om;
    const bool doSig = (z != 2);
    const bool doCsum = (z == 3);

    auto load_stage = [&](int s, int kt) {
        const int kofs = kt * KCHUNK;
        const uint32_t dstA = sbase + s * STAGE_BYTES;
        const uint32_t dstB = dstA + TILE_BYTES;
        #pragma unroll
        for (int i = 0; i < 8; i++) {
            const int idx = tid + i * 256;
            const int r = (idx & 1023) >> 3;
            const int c = idx & 7;
            const __half* src = (idx < 1024 ? Ab : Wb) + (size_t)r * KDIM + kofs + c * 8;
            const uint32_t dst = (idx < 1024 ? dstA : dstB) + r * ROWB + c * 16;
            cpasync16(dst, src);
        }
        asm volatile("cp.async.commit_group;" ::: "memory");
    };

    load_stage(0, 0); load_stage(1, 1);

    float c[2][8][4];
    #pragma unroll
    for (int mi = 0; mi < 2; mi++)
        #pragma unroll
        for (int ni = 0; ni < 8; ni++)
            #pragma unroll
            for (int j = 0; j < 4; j++) c[mi][ni][j] = 0.f;

    gemm_mainloop(c, sbase, tid, lane, wm, wn, load_stage);

    float* colacc = (float*)smem;
    if (doCsum) {
        __syncthreads();
        if (tid < 128) colacc[tid] = 0.f;
        __syncthreads();
    }
    const int quad = lane >> 2, qt = lane & 3;
    #pragma unroll
    for (int ni = 0; ni < 8; ni++) {
        const int o = colBase + wn * 64 + ni * 8 + qt * 2;
        const float b0 = bias[o], b1 = bias[o + 1];
        float sx = 0.f, sy = 0.f;
        #pragma unroll
        for (int mi = 0; mi < 2; mi++) {
            #pragma unroll
            for (int half = 0; half < 2; half++) {
                const int m = rowBase + wm * 32 + mi * 16 + quad + half * 8;
                float2 v;
                v.x = c[mi][ni][half*2]     + b0;
                v.y = c[mi][ni][half*2 + 1] + b1;
                if (doSig) { v.x = sigm(v.x); v.y = sigm(v.y); }
                sx += v.x; sy += v.y;
                const int bb = m >> 12, n = m & (N_ - 1);
                *(float2*)(out + (((size_t)(bb * H_ + (o >> 6))) * N_ + n) * D_ + (o & 63)) = v;
            }
        }
        if (doCsum) {
            const int lo = wn * 64 + ni * 8 + qt * 2;
            atomicAdd(&colacc[lo], sx);
            atomicAdd(&colacc[lo + 1], sy);
        }
    }
    if (doCsum) {
        __syncthreads();
        if (tid < 128) {
            const int b = rowBase >> 12;
            const int o = colBase + tid;
            atomicAdd(&g_msum[(b * H_ + (o >> 6)) * D_ + (o & 63)], colacc[tid]);
        }
    }
}

// ---------------- output GEMM ----------------
__global__ void __launch_bounds__(256, 2)
gemm_out(const __half* __restrict__ A, const __half* __restrict__ W,
         const float* __restrict__ bias, float* __restrict__ out) {
    extern __shared__ char smem[];
    const uint32_t sbase = smem_u32(smem);
    const int tid = threadIdx.x;
    const int lane = tid & 31, w = tid >> 5;
    const int wm = w & 3, wn = w >> 2;
    const int rowBase = blockIdx.y * 128, colBase = blockIdx.x * 128;
    const __half* Ab = A + (size_t)rowBase * KDIM;
    const __half* Wb = W + (size_t)colBase * KDIM;

    auto load_stage = [&](int s, int kt) {
        const int kofs = kt * KCHUNK;
        const uint32_t dstA = sbase + s * STAGE_BYTES;
        const uint32_t dstB = dstA + TILE_BYTES;
        #pragma unroll
        for (int i = 0; i < 8; i++) {
            const int idx = tid + i * 256;
            const int r = (idx & 1023) >> 3;
            const int c = idx & 7;
            const __half* src = (idx < 1024 ? Ab : Wb) + (size_t)r * KDIM + kofs + c * 8;
            const uint32_t dst = (idx < 1024 ? dstA : dstB) + r * ROWB + c * 16;
            cpasync16(dst, src);
        }
        asm volatile("cp.async.commit_group;" ::: "memory");
    };

    load_stage(0, 0); load_stage(1, 1);

    float c[2][8][4];
    #pragma unroll
    for (int mi = 0; mi < 2; mi++)
        #pragma unroll
        for (int ni = 0; ni < 8; ni++)
            #pragma unroll
            for (int j = 0; j < 4; j++) c[mi][ni][j] = 0.f;

    gemm_mainloop(c, sbase, tid, lane, wm, wn, load_stage);

    const int quad = lane >> 2, qt = lane & 3;
    #pragma unroll
    for (int ni = 0; ni < 8; ni++) {
        const int o = colBase + wn * 64 + ni * 8 + qt * 2;
        const float b0 = bias[o], b1 = bias[o + 1];
        #pragma unroll
        for (int mi = 0; mi < 2; mi++) {
            #pragma unroll
            for (int half = 0; half < 2; half++) {
                const int m = rowBase + wm * 32 + mi * 16 + quad + half * 8;
                float2 v;
                v.x = c[mi][ni][half*2]     + b0;
                v.y = c[mi][ni][half*2 + 1] + b1;
                *(float2*)(out + (size_t)m * C_ + o) = v;
            }
        }
    }
}

// ---------------- fused flow core: 5 phases, software grid barriers ----------------
__device__ __forceinline__ void grid_bar(int phase) {
    __threadfence();
    __syncthreads();
    if (threadIdx.x == 0) {
        atomicAdd(&g_flowbar, 1u);
        const unsigned target = (unsigned)(FLOW_GRID * phase);
        while (*(volatile unsigned*)&g_flowbar < target) { }
        __threadfence();
    }
    __syncthreads();
}

__global__ void __launch_bounds__(256, 4)
flow_fused() {
    const int bh = blockIdx.x;
    const int y = blockIdx.y;
    const int rows0 = y * FLOW_ROWS;
    const int tid = threadIdx.x, lane = tid & 31, warp = tid >> 5;
    const int halfl = lane >> 4, lc = (lane & 15) * 4;
    const size_t base = (size_t)bh * N_ * D_;

    __shared__ union {
        struct { float s0[64], s1[64]; float partq[8][64], partk[8][64]; } p;
        struct { float skso[64], sqsi[64]; float sk[16][64], sv[16][64], escs[16]; } fg;
        struct { float sagg[64][64]; float sq[64][65]; } xo;
    } sm;

    // ================= phase 1: eq/ek + qesum/kesum =================
    {
        if (tid < 64) sm.p.s0[tid] = g_msum[bh * 64 + tid] + EPS_;
        __syncthreads();
        const float4 ms = *(const float4*)&sm.p.s0[lc];
        float aq[4] = {0,0,0,0}, ak[4] = {0,0,0,0};
        #pragma unroll 4
        for (int it = 0; it < FLOW_ROWS / 16; it++) {
            const int n = rows0 + it * 16 + warp * 2 + halfl;
            float4 q = *(const float4*)(g_qh + base + (size_t)n * D_ + lc);
            float4 k = *(const float4*)(g_kh + base + (size_t)n * D_ + lc);
            float dq = (q.x+EPS_)*ms.x + (q.y+EPS_)*ms.y + (q.z+EPS_)*ms.z + (q.w+EPS_)*ms.w;
            float dk = (k.x+EPS_)*ms.x + (k.y+EPS_)*ms.y + (k.z+EPS_)*ms.z + (k.w+EPS_)*ms.w;
            #pragma unroll
            for (int o = 8; o; o >>= 1) {
                dq += __shfl_xor_sync(0xffffffffu, dq, o);
                dk += __shfl_xor_sync(0xffffffffu, dk, o);
            }
            const float eq = 1.f / (dq + EPS_), ek = 1.f / (dk + EPS_);
            aq[0] += q.x*eq; aq[1] += q.y*eq; aq[2] += q.z*eq; aq[3] += q.w*eq;
            ak[0] += k.x*ek; ak[1] += k.y*ek; ak[2] += k.z*ek; ak[3] += k.w*ek;
        }
        #pragma unroll
        for (int j = 0; j < 4; j++) {
            aq[j] += __shfl_xor_sync(0xffffffffu, aq[j], 16);
            ak[j] += __shfl_xor_sync(0xffffffffu, ak[j], 16);
        }
        __syncthreads();
        if (halfl == 0) {
            #pragma unroll
            for (int j = 0; j < 4; j++) { sm.p.partq[warp][lc+j] = aq[j]; sm.p.partk[warp][lc+j] = ak[j]; }
        }
        __syncthreads();
        if (tid < 64) {
            float s = 0.f;
            #pragma unroll
            for (int w = 0; w < 8; w++) s += sm.p.partq[w][tid];
            atomicAdd(&g_qesum[bh * 64 + tid], s);
        } else if (tid < 128) {
            const int j = tid - 64;
            float s = 0.f;
            #pragma unroll
            for (int w = 0; w < 8; w++) s += sm.p.partk[w][j];
            atomicAdd(&g_kesum[bh * 64 + j], s);
        }
    }
    grid_bar(1);

    // ================= phase 2: eqq/ekk + in-place update + qhsum/khsum =================
    {
        if (tid < 64) { sm.p.s0[tid] = g_qesum[bh * 64 + tid] + EPS_; sm.p.s1[tid] = g_kesum[bh * 64 + tid] + EPS_; }
        __syncthreads();
        const float4 vq = *(const float4*)&sm.p.s0[lc];
        const float4 vk = *(const float4*)&sm.p.s1[lc];
        float aq[4] = {0,0,0,0}, ak[4] = {0,0,0,0};
        #pragma unroll 4
        for (int it = 0; it < FLOW_ROWS / 16; it++) {
            const int n = rows0 + it * 16 + warp * 2 + halfl;
            float4 m = *(const float4*)(g_mh + base + (size_t)n * D_ + lc);
            float dq = (m.x+EPS_)*vq.x + (m.y+EPS_)*vq.y + (m.z+EPS_)*vq.z + (m.w+EPS_)*vq.w;
            float dk = (m.x+EPS_)*vk.x + (m.y+EPS_)*vk.y + (m.z+EPS_)*vk.z + (m.w+EPS_)*vk.w;
            #pragma unroll
            for (int o = 8; o; o >>= 1) {
                dq += __shfl_xor_sync(0xffffffffu, dq, o);
                dk += __shfl_xor_sync(0xffffffffu, dk, o);
            }
            const float tq = sigm(dq + EPS_), tk = sigm(dk + EPS_);
            float4* qp = (float4*)(g_qh + base + (size_t)n * D_ + lc);
            float4* kp = (float4*)(g_kh + base + (size_t)n * D_ + lc);
            float4 q = *qp, k = *kp;
            q.x *= (1.f + m.x*tq); q.y *= (1.f + m.y*tq); q.z *= (1.f + m.z*tq); q.w *= (1.f + m.w*tq);
            k.x *= (1.f + m.x*tk); k.y *= (1.f + m.y*tk); k.z *= (1.f + m.z*tk); k.w *= (1.f + m.w*tk);
            *qp = q; *kp = k;
            aq[0] += q.x; aq[1] += q.y; aq[2] += q.z; aq[3] += q.w;
            ak[0] += k.x; ak[1] += k.y; ak[2] += k.z; ak[3] += k.w;
        }
        #pragma unroll
        for (int j = 0; j < 4; j++) {
            aq[j] += __shfl_xor_sync(0xffffffffu, aq[j], 16);
            ak[j] += __shfl_xor_sync(0xffffffffu, ak[j], 16);
        }
        __syncthreads();
        if (halfl == 0) {
            #pragma unroll
            for (int j = 0; j < 4; j++) { sm.p.partq[warp][lc+j] = aq[j]; sm.p.partk[warp][lc+j] = ak[j]; }
        }
        __syncthreads();
        if (tid < 64) {
            float s = 0.f;
            #pragma unroll
            for (int w = 0; w < 8; w++) s += sm.p.partq[w][tid];
            atomicAdd(&g_qhsum[bh * 64 + tid], s);
        } else if (tid < 128) {
            const int j = tid - 64;
            float s = 0.f;
            #pragma unroll
            for (int w = 0; w < 8; w++) s += sm.p.partk[w][j];
            atomicAdd(&g_khsum[bh * 64 + j], s);
        }
    }
    grid_bar(2);

    // ================= phase 3: si/so + qsisum/ksosum =================
    {
        if (tid < 64) { sm.p.s0[tid] = g_khsum[bh * 64 + tid] + EPS_; sm.p.s1[tid] = g_qhsum[bh * 64 + tid] + EPS_; }
        __syncthreads();
        const float4 vkh = *(const float4*)&sm.p.s0[lc];
        const float4 vqh = *(const float4*)&sm.p.s1[lc];
        float aq[4] = {0,0,0,0}, ak[4] = {0,0,0,0};
        #pragma unroll 4
        for (int it = 0; it < FLOW_ROWS / 16; it++) {
            const int n = rows0 + it * 16 + warp * 2 + halfl;
            float4 q = *(const float4*)(g_qh + base + (size_t)n * D_ + lc);
            float4 k = *(const float4*)(g_kh + base + (size_t)n * D_ + lc);
            float di = (q.x+EPS_)*vkh.x + (q.y+EPS_)*vkh.y + (q.z+EPS_)*vkh.z + (q.w+EPS_)*vkh.w;
            float dz = (k.x+EPS_)*vqh.x + (k.y+EPS_)*vqh.y + (k.z+EPS_)*vqh.z + (k.w+EPS_)*vqh.w;
            #pragma unroll
            for (int o = 8; o; o >>= 1) {
                di += __shfl_xor_sync(0xffffffffu, di, o);
                dz += __shfl_xor_sync(0xffffffffu, dz, o);
            }
            const float si = 1.f / (di + EPS_), so = 1.f / (dz + EPS_);
            if ((lane & 15) == 0) g_si[bh * N_ + n] = si;
            aq[0] += q.x*si; aq[1] += q.y*si; aq[2] += q.z*si; aq[3] += q.w*si;
            ak[0] += k.x*so; ak[1] += k.y*so; ak[2] += k.z*so; ak[3] += k.w*so;
        }
        #pragma unroll
        for (int j = 0; j < 4; j++) {
            aq[j] += __shfl_xor_sync(0xffffffffu, aq[j], 16);
            ak[j] += __shfl_xor_sync(0xffffffffu, ak[j], 16);
        }
        __syncthreads();
        if (halfl == 0) {
            #pragma unroll
            for (int j = 0; j < 4; j++) { sm.p.partq[warp][lc+j] = aq[j]; sm.p.partk[warp][lc+j] = ak[j]; }
        }
        __syncthreads();
        if (tid < 64) {
            float s = 0.f;
            #pragma unroll
            for (int w = 0; w < 8; w++) s += sm.p.partq[w][tid];
            atomicAdd(&g_qsisum[bh * 64 + tid], s);
        } else if (tid < 128) {
            const int j = tid - 64;
            float s = 0.f;
            #pragma unroll
            for (int w = 0; w < 8; w++) s += sm.p.partk[w][j];
            atomicAdd(&g_ksosum[bh * 64 + j], s);
        }
    }
    grid_bar(3);

    // ================= phase 4: conserved scalars + kv_agg =================
    {
        const int tx = tid & 15, ty = tid >> 4;
        if (tid < 64) { sm.fg.skso[tid] = g_ksosum[bh * 64 + tid] + EPS_; sm.fg.sqsi[tid] = g_qsisum[bh * 64 + tid] + EPS_; }
        __syncthreads();
        const float a0 = sm.fg.skso[lane*2], a1 = sm.fg.skso[lane*2+1];
        const float b0 = sm.fg.sqsi[lane*2], b1 = sm.fg.sqsi[lane*2+1];
        float acc[4][4];
        #pragma unroll
        for (int i = 0; i < 4; i++)
            #pragma unroll
            for (int j = 0; j < 4; j++) acc[i][j] = 0.f;
        float sumexp_loc = 0.f;

        for (int c = 0; c < FLOW_ROWS; c += 16) {
            #pragma unroll
            for (int i = 0; i < 4; i++) {
                const int li = tid + i * 256;
                const int r = li >> 6, d = li & 63;
                const int n = rows0 + c + r;
                sm.fg.sk[r][d] = g_kh[base + (size_t)n * D_ + d];
                sm.fg.sv[r][d] = g_vh[base + (size_t)n * D_ + d];
            }
            __syncthreads();
            #pragma unroll
            for (int rr = 0; rr < 2; rr++) {
                const int r = warp * 2 + rr;
                const int n = rows0 + c + r;
                float2 q2 = *(const float2*)(g_qh + base + (size_t)n * D_ + lane * 2);
                const float kx = sm.fg.sk[r][lane*2], ky = sm.fg.sk[r][lane*2+1];
                float dq = (q2.x + EPS_) * a0 + (q2.y + EPS_) * a1;
                float dk = (kx + EPS_) * b0 + (ky + EPS_) * b1;
                #pragma unroll
                for (int o = 16; o; o >>= 1) {
                    dq += __shfl_xor_sync(0xffffffffu, dq, o);
                    dk += __shfl_xor_sync(0xffffffffu, dk, o);
                }
                if (lane == 0) {
                    const float csink = dq + EPS_;
                    float cs = fminf(fmaxf(dk + EPS_, -1.f), 1.f);
                    const float e = __expf(cs);
                    sm.fg.escs[r] = e;
                    sumexp_loc += e;
                    const int idx = bh * N_ + n;
                    g_ssink[idx] = g_si[idx] * sigm(csink);
                }
            }
            __syncthreads();
            #pragma unroll
            for (int r = 0; r < 16; r++) {
                const float es = sm.fg.escs[r];
                const float4 kk = ((const float4*)sm.fg.sk[r])[ty];
                float4 vv = ((const float4*)sm.fg.sv[r])[tx];
                vv.x *= es; vv.y *= es; vv.z *= es; vv.w *= es;
                acc[0][0] += kk.x*vv.x; acc[0][1] += kk.x*vv.y; acc[0][2] += kk.x*vv.z; acc[0][3] += kk.x*vv.w;
                acc[1][0] += kk.y*vv.x; acc[1][1] += kk.y*vv.y; acc[1][2] += kk.y*vv.z; acc[1][3] += kk.y*vv.w;
                acc[2][0] += kk.z*vv.x; acc[2][1] += kk.z*vv.y; acc[2][2] += kk.z*vv.z; acc[2][3] += kk.z*vv.w;
                acc[3][0] += kk.w*vv.x; acc[3][1] += kk.w*vv.y; acc[3][2] += kk.w*vv.z; acc[3][3] += kk.w*vv.w;
            }
            __syncthreads();
        }
        #pragma unroll
        for (int i = 0; i < 4; i++)
            #pragma unroll
            for (int j = 0; j < 4; j++)
                atomicAdd(&g_agg[bh * 4096 + (ty * 4 + i) * 64 + tx * 4 + j], acc[i][j]);
        if (lane == 0) atomicAdd(&g_sumexp[bh], sumexp_loc);
    }
    grid_bar(4);

    // ================= phase 5: x = (qh @ agg) * ssink * (N/sumexp) -> fp16 g_ah =================
    {
        const int b = bh / H_, h = bh % H_;
        const float scl = (float)N_ / g_sumexp[bh];
        #pragma unroll
        for (int i = 0; i < 16; i++) {
            const int li = tid + i * 256;
            sm.xo.sagg[li >> 6][li & 63] = g_agg[bh * 4096 + li];
        }
        __syncthreads();
        for (int t = 0; t < FLOW_ROWS / 64; t++) {
            const size_t tbase = base + (size_t)(rows0 + t * 64) * D_;
            #pragma unroll
            for (int i = 0; i < 4; i++) {
                const int li = tid + i * 256;
                const int r = li >> 4, c4 = li & 15;
                float4 v = *(const float4*)(g_qh + tbase + (size_t)r * D_ + c4 * 4);
                sm.xo.sq[r][c4*4+0] = v.x; sm.xo.sq[r][c4*4+1] = v.y;
                sm.xo.sq[r][c4*4+2] = v.z; sm.xo.sq[r][c4*4+3] = v.w;
            }
            __syncthreads();
            const int r = tid >> 2, ch = tid & 3;
            float acc[16];
            #pragma unroll
            for (int j = 0; j < 16; j++) acc[j] = 0.f;
            #pragma unroll 8
            for (int d = 0; d < 64; d++) {
                const float qv = sm.xo.sq[r][d];
                const float4* ag = (const float4*)(&sm.xo.sagg[d][ch * 16]);
                #pragma unroll
                for (int j4 = 0; j4 < 4; j4++) {
                    float4 av = ag[j4];
                    acc[j4*4+0] += qv * av.x; acc[j4*4+1] += qv * av.y;
                    acc[j4*4+2] += qv * av.z; acc[j4*4+3] += qv * av.w;
                }
            }
            const int n = rows0 + t * 64 + r;
            const float s = g_ssink[bh * N_ + n] * scl;
            __half* xr = g_ah + ((size_t)b * N_ + n) * C_ + h * 64 + ch * 16;
            uint32_t u[8];
            #pragma unroll
            for (int j = 0; j < 8; j++) {
                __half2 hh = __floats2half2_rn(acc[2*j] * s, acc[2*j+1] * s);
                u[j] = *(uint32_t*)&hh;
            }
            ((uint4*)xr)[0] = make_uint4(u[0], u[1], u[2], u[3]);
            ((uint4*)xr)[1] = make_uint4(u[4], u[5], u[6], u[7]);
            __syncthreads();
        }
    }
}

// ---------------- launch ----------------
extern "C" void kernel_launch(void* const* d_in, const int* in_sizes, int n_in,
                              void* d_out, int out_size) {
    const float* q      = (const float*)d_in[0];
    const float* kv     = (const float*)d_in[1];
    const float* motion = (const float*)d_in[2];
    const float* Wq = (const float*)d_in[3];  const float* bq = (const float*)d_in[4];
    const float* Wk = (const float*)d_in[5];  const float* bk = (const float*)d_in[6];
    const float* Wv = (const float*)d_in[7];  const float* bv = (const float*)d_in[8];
    const float* Wm = (const float*)d_in[9];  const float* bm = (const float*)d_in[10];
    const float* Wo = (const float*)d_in[11]; const float* bo = (const float*)d_in[12];
    float* out = (float*)d_out;

    float *p_qh, *p_kh, *p_vh, *p_mh;
    __half *p_ah, *p_wh;
    cudaGetSymbolAddress((void**)&p_qh, g_qh);
    cudaGetSymbolAddress((void**)&p_kh, g_kh);
    cudaGetSymbolAddress((void**)&p_vh, g_vh);
    cudaGetSymbolAddress((void**)&p_mh, g_mh);
    cudaGetSymbolAddress((void**)&p_ah, g_ah);
    cudaGetSymbolAddress((void**)&p_wh, g_wh);

    cudaFuncSetAttribute(gemm_proj, cudaFuncAttributeMaxDynamicSharedMemorySize, GEMM_SMEM);
    cudaFuncSetAttribute(gemm_out,  cudaFuncAttributeMaxDynamicSharedMemorySize, GEMM_SMEM);

    const dim3 gProj(C_ / 128, M_ / 128, 4);
    const dim3 gOut(C_ / 128, M_ / 128);
    const int actN4 = M_ * C_ / 4;
    const int wN4   = C_ * C_ / 4;
    const int actBlk = (actN4 + 255) / 256;
    const int wBlk   = (wN4 + 255) / 256;
    const size_t WS = (size_t)C_ * C_;

    zero_kernel<<<(BH_*D_*D_ + 255) / 256, 256>>>();
    f2h_w5_kernel<<<dim3(wBlk, 5), 256>>>(Wq, Wk, Wv, Wm, Wo, p_wh);
    f2h_acts_kernel<<<dim3(actBlk, 3), 256>>>(q, kv, motion, p_ah);

    gemm_proj<<<gProj, 256, GEMM_SMEM>>>(p_ah, p_wh, bq, bk, bv, bm, p_qh, p_kh, p_vh, p_mh);

    flow_fused<<<dim3(BH_, FLOW_Y), 256>>>();

    gemm_out<<<gOut, 256, GEMM_SMEM>>>(p_ah, p_wh + 4*WS, bo, out);
}

// round 16
// speedup vs baseline: 1.1421x; 1.1421x over previous
#include <cuda_runtime.h>
#include <cuda_fp16.h>
#include <cstdint>
#include <math.h>

#define B_ 4
#define N_ 4096
#define C_ 768
#define H_ 12
#define D_ 64
#define BH_ 48
#define M_ (B_*N_)
#define EPS_ 1e-6f
#define SPLIT_ 32
#define ROWS_PB (N_/SPLIT_)   // 128

// ---- mma.sync GEMM config (R12/R14 best) ----
#define KDIM 768
#define KCHUNK 64
#define NCHUNKS 12
#define ROWH 72
#define ROWB (ROWH*2)
#define TILE_BYTES (128*ROWB)
#define STAGE_BYTES (2*TILE_BYTES)
#define GEMM_SMEM (3*STAGE_BYTES)    // 110592

// ---------------- scratch (flow intermediates now fp16) ----------------
__device__ __half g_qh[BH_*N_*D_];
__device__ __half g_kh[BH_*N_*D_];
__device__ __half g_vh[BH_*N_*D_];
__device__ __half g_mh[BH_*N_*D_];
__device__ float g_msum[BH_*D_];
__device__ float g_qesum[BH_*D_];
__device__ float g_kesum[BH_*D_];
__device__ float g_qhsum[BH_*D_];
__device__ float g_khsum[BH_*D_];
__device__ float g_qsisum[BH_*D_];
__device__ float g_ksosum[BH_*D_];
__device__ float g_si[BH_*N_];
__device__ float g_ssink[BH_*N_];
__device__ float g_sumexp[BH_];
__device__ float g_agg[BH_*D_*D_];
__device__ __half g_ah[(size_t)3*M_*C_];
__device__ __half g_wh[(size_t)5*C_*C_];

__device__ __forceinline__ float sigm(float x) { return 1.f / (1.f + __expf(-x)); }

__device__ __forceinline__ uint32_t smem_u32(const void* p) {
    uint32_t a;
    asm("{ .reg .u64 t; cvta.to.shared.u64 t, %1; cvt.u32.u64 %0, t; }" : "=r"(a) : "l"(p));
    return a;
}
__device__ __forceinline__ void cpasync16(uint32_t dst, const void* src) {
    asm volatile("cp.async.cg.shared.global [%0], [%1], 16;" :: "r"(dst), "l"(src) : "memory");
}
#define LDSM4(r0,r1,r2,r3,addr) \
    asm volatile("ldmatrix.sync.aligned.m8n8.x4.shared.b16 {%0,%1,%2,%3}, [%4];" \
        : "=r"(r0),"=r"(r1),"=r"(r2),"=r"(r3) : "r"(addr))
#define MMA16816(c, a, b0, b1) \
    asm volatile("mma.sync.aligned.m16n8k16.row.col.f32.f16.f16.f32 " \
        "{%0,%1,%2,%3}, {%4,%5,%6,%7}, {%8,%9}, {%0,%1,%2,%3};" \
        : "+f"((c)[0]),"+f"((c)[1]),"+f"((c)[2]),"+f"((c)[3]) \
        : "r"((a)[0]),"r"((a)[1]),"r"((a)[2]),"r"((a)[3]),"r"(b0),"r"(b1))

// half8 load helper: 8 halves -> 8 floats
__device__ __forceinline__ void ld_h8(const __half* p, float* f) {
    uint4 u = *(const uint4*)p;
    float2 a = __half22float2(*(__half2*)&u.x);
    float2 b = __half22float2(*(__half2*)&u.y);
    float2 c = __half22float2(*(__half2*)&u.z);
    float2 d = __half22float2(*(__half2*)&u.w);
    f[0]=a.x; f[1]=a.y; f[2]=b.x; f[3]=b.y; f[4]=c.x; f[5]=c.y; f[6]=d.x; f[7]=d.y;
}
__device__ __forceinline__ void st_h8(__half* p, const float* f) {
    uint4 u;
    __half2 h0 = __floats2half2_rn(f[0], f[1]);
    __half2 h1 = __floats2half2_rn(f[2], f[3]);
    __half2 h2 = __floats2half2_rn(f[4], f[5]);
    __half2 h3 = __floats2half2_rn(f[6], f[7]);
    u.x = *(uint32_t*)&h0; u.y = *(uint32_t*)&h1; u.z = *(uint32_t*)&h2; u.w = *(uint32_t*)&h3;
    *(uint4*)p = u;
}

// ---------------- zero accumulators ----------------
__global__ void zero_kernel() {
    int i = blockIdx.x * blockDim.x + threadIdx.x;
    if (i < BH_*D_) {
        g_msum[i] = 0.f; g_qesum[i] = 0.f; g_kesum[i] = 0.f;
        g_qhsum[i] = 0.f; g_khsum[i] = 0.f; g_qsisum[i] = 0.f; g_ksosum[i] = 0.f;
    }
    if (i < BH_) g_sumexp[i] = 0.f;
    if (i < BH_*D_*D_) g_agg[i] = 0.f;
}

// ---------------- fp32 -> fp16 ----------------
__global__ void f2h_acts_kernel(const float* a0, const float* a1, const float* a2,
                                __half* __restrict__ dst) {
    const int n4 = M_ * C_ / 4;
    int i = blockIdx.x * 256 + threadIdx.x;
    if (i >= n4) return;
    const float* src = blockIdx.y == 0 ? a0 : blockIdx.y == 1 ? a1 : a2;
    float4 v = ((const float4*)src)[i];
    __half* d = dst + (size_t)blockIdx.y * M_ * C_;
    ((__half2*)d)[i*2]   = __floats2half2_rn(v.x, v.y);
    ((__half2*)d)[i*2+1] = __floats2half2_rn(v.z, v.w);
}
__global__ void f2h_w5_kernel(const float* w0, const float* w1, const float* w2,
                              const float* w3, const float* w4, __half* __restrict__ dst) {
    const int n4 = C_ * C_ / 4;
    int i = blockIdx.x * 256 + threadIdx.x;
    if (i >= n4) return;
    const float* src = blockIdx.y == 0 ? w0 : blockIdx.y == 1 ? w1 : blockIdx.y == 2 ? w2
                     : blockIdx.y == 3 ? w3 : w4;
    float4 v = ((const float4*)src)[i];
    __half* d = dst + (size_t)blockIdx.y * C_ * C_;
    ((__half2*)d)[i*2]   = __floats2half2_rn(v.x, v.y);
    ((__half2*)d)[i*2+1] = __floats2half2_rn(v.z, v.w);
}

// ---------------- GEMM mainloop (R12/R14) ----------------
template<typename LoaderT>
__device__ __forceinline__ void gemm_mainloop(
    float c[2][8][4], const uint32_t sbase, const int tid, const int lane,
    const int wm, const int wn, LoaderT load_stage) {
    const int lrow = lane & 15;
    const int lkof = (lane >> 4) * 8;
    const uint32_t rowOffA = (wm * 32 + lrow) * ROWB;

    uint32_t af[2][8], bf[2][16];

    for (int kt = 0; kt < NCHUNKS; kt++) {
        if (kt + 1 < NCHUNKS) asm volatile("cp.async.wait_group 1;" ::: "memory");
        else                  asm volatile("cp.async.wait_group 0;" ::: "memory");
        __syncthreads();
        const int s = kt % 3;
        const uint32_t aBase = sbase + s * STAGE_BYTES;
        const uint32_t bBase = aBase + TILE_BYTES;
        if (kt + 2 < NCHUNKS) load_stage((kt + 2) % 3, kt + 2);

        {
            const uint32_t kb = lkof * 2;
            const uint32_t aA = aBase + rowOffA + kb;
            LDSM4(af[0][0], af[0][1], af[0][2], af[0][3], aA);
            LDSM4(af[0][4], af[0][5], af[0][6], af[0][7], aA + 16 * ROWB);
            #pragma unroll
            for (int nb = 0; nb < 4; nb++) {
                const uint32_t aB = bBase + (wn * 64 + nb * 16 + lrow) * ROWB + kb;
                LDSM4(bf[0][nb*4+0], bf[0][nb*4+1], bf[0][nb*4+2], bf[0][nb*4+3], aB);
            }
        }
        #pragma unroll
        for (int ks = 0; ks < 4; ks++) {
            const int cur = ks & 1, nxt = cur ^ 1;
            if (ks < 3) {
                const uint32_t kb = ((ks + 1) * 16 + lkof) * 2;
                const uint32_t aA = aBase + rowOffA + kb;
                LDSM4(af[nxt][0], af[nxt][1], af[nxt][2], af[nxt][3], aA);
                LDSM4(af[nxt][4], af[nxt][5], af[nxt][6], af[nxt][7], aA + 16 * ROWB);
                #pragma unroll
                for (int nb = 0; nb < 4; nb++) {
                    const uint32_t aB = bBase + (wn * 64 + nb * 16 + lrow) * ROWB + kb;
                    LDSM4(bf[nxt][nb*4+0], bf[nxt][nb*4+1], bf[nxt][nb*4+2], bf[nxt][nb*4+3], aB);
                }
            }
            #pragma unroll
            for (int nb = 0; nb < 4; nb++) {
                MMA16816(c[0][2*nb],   af[cur],     bf[cur][nb*4+0], bf[cur][nb*4+2]);
                MMA16816(c[1][2*nb],   af[cur] + 4, bf[cur][nb*4+0], bf[cur][nb*4+2]);
                MMA16816(c[0][2*nb+1], af[cur],     bf[cur][nb*4+1], bf[cur][nb*4+3]);
                MMA16816(c[1][2*nb+1], af[cur] + 4, bf[cur][nb*4+1], bf[cur][nb*4+3]);
            }
        }
    }
}

// ---------------- merged projection GEMM (epilogue writes fp16 head layout) ----------------
__global__ void __launch_bounds__(256, 2)
gemm_proj(const __half* __restrict__ Aall, const __half* __restrict__ Wall,
          const float* __restrict__ bq, const float* __restrict__ bk,
          const float* __restrict__ bv, const float* __restrict__ bm,
          __half* __restrict__ oq, __half* __restrict__ ok,
          __half* __restrict__ ov, __half* __restrict__ om) {
    extern __shared__ char smem[];
    const uint32_t sbase = smem_u32(smem);
    const int tid = threadIdx.x;
    const int lane = tid & 31, w = tid >> 5;
    const int wm = w & 3, wn = w >> 2;
    const int z = blockIdx.z;
    const int rowBase = blockIdx.y * 128, colBase = blockIdx.x * 128;
    const int aslot = (z == 0) ? 0 : (z == 3) ? 2 : 1;
    const __half* Ab = Aall + (size_t)aslot * M_ * C_ + (size_t)rowBase * KDIM;
    const __half* Wb = Wall + (size_t)z * C_ * C_ + (size_t)colBase * KDIM;
    const float* bias = (z == 0) ? bq : (z == 1) ? bk : (z == 2) ? bv : bm;
    __half* out = (z == 0) ? oq : (z == 1) ? ok : (z == 2) ? ov : om;
    const bool doSig = (z != 2);
    const bool doCsum = (z == 3);

    auto load_stage = [&](int s, int kt) {
        const int kofs = kt * KCHUNK;
        const uint32_t dstA = sbase + s * STAGE_BYTES;
        const uint32_t dstB = dstA + TILE_BYTES;
        #pragma unroll
        for (int i = 0; i < 8; i++) {
            const int idx = tid + i * 256;
            const int r = (idx & 1023) >> 3;
            const int c = idx & 7;
            const __half* src = (idx < 1024 ? Ab : Wb) + (size_t)r * KDIM + kofs + c * 8;
            const uint32_t dst = (idx < 1024 ? dstA : dstB) + r * ROWB + c * 16;
            cpasync16(dst, src);
        }
        asm volatile("cp.async.commit_group;" ::: "memory");
    };

    load_stage(0, 0); load_stage(1, 1);

    float c[2][8][4];
    #pragma unroll
    for (int mi = 0; mi < 2; mi++)
        #pragma unroll
        for (int ni = 0; ni < 8; ni++)
            #pragma unroll
            for (int j = 0; j < 4; j++) c[mi][ni][j] = 0.f;

    gemm_mainloop(c, sbase, tid, lane, wm, wn, load_stage);

    float* colacc = (float*)smem;
    if (doCsum) {
        __syncthreads();
        if (tid < 128) colacc[tid] = 0.f;
        __syncthreads();
    }
    const int quad = lane >> 2, qt = lane & 3;
    #pragma unroll
    for (int ni = 0; ni < 8; ni++) {
        const int o = colBase + wn * 64 + ni * 8 + qt * 2;
        const float b0 = bias[o], b1 = bias[o + 1];
        float sx = 0.f, sy = 0.f;
        #pragma unroll
        for (int mi = 0; mi < 2; mi++) {
            #pragma unroll
            for (int half = 0; half < 2; half++) {
                const int m = rowBase + wm * 32 + mi * 16 + quad + half * 8;
                float vx = c[mi][ni][half*2]     + b0;
                float vy = c[mi][ni][half*2 + 1] + b1;
                if (doSig) { vx = sigm(vx); vy = sigm(vy); }
                sx += vx; sy += vy;
                const int bb = m >> 12, n = m & (N_ - 1);
                __half2 hv = __floats2half2_rn(vx, vy);
                *(__half2*)(out + (((size_t)(bb * H_ + (o >> 6))) * N_ + n) * D_ + (o & 63)) = hv;
            }
        }
        if (doCsum) {
            const int lo = wn * 64 + ni * 8 + qt * 2;
            atomicAdd(&colacc[lo], sx);
            atomicAdd(&colacc[lo + 1], sy);
        }
    }
    if (doCsum) {
        __syncthreads();
        if (tid < 128) {
            const int b = rowBase >> 12;
            const int o = colBase + tid;
            atomicAdd(&g_msum[(b * H_ + (o >> 6)) * D_ + (o & 63)], colacc[tid]);
        }
    }
}

// ---------------- output GEMM (unchanged: fp16 in, fp32 out) ----------------
__global__ void __launch_bounds__(256, 2)
gemm_out(const __half* __restrict__ A, const __half* __restrict__ W,
         const float* __restrict__ bias, float* __restrict__ out) {
    extern __shared__ char smem[];
    const uint32_t sbase = smem_u32(smem);
    const int tid = threadIdx.x;
    const int lane = tid & 31, w = tid >> 5;
    const int wm = w & 3, wn = w >> 2;
    const int rowBase = blockIdx.y * 128, colBase = blockIdx.x * 128;
    const __half* Ab = A + (size_t)rowBase * KDIM;
    const __half* Wb = W + (size_t)colBase * KDIM;

    auto load_stage = [&](int s, int kt) {
        const int kofs = kt * KCHUNK;
        const uint32_t dstA = sbase + s * STAGE_BYTES;
        const uint32_t dstB = dstA + TILE_BYTES;
        #pragma unroll
        for (int i = 0; i < 8; i++) {
            const int idx = tid + i * 256;
            const int r = (idx & 1023) >> 3;
            const int c = idx & 7;
            const __half* src = (idx < 1024 ? Ab : Wb) + (size_t)r * KDIM + kofs + c * 8;
            const uint32_t dst = (idx < 1024 ? dstA : dstB) + r * ROWB + c * 16;
            cpasync16(dst, src);
        }
        asm volatile("cp.async.commit_group;" ::: "memory");
    };

    load_stage(0, 0); load_stage(1, 1);

    float c[2][8][4];
    #pragma unroll
    for (int mi = 0; mi < 2; mi++)
        #pragma unroll
        for (int ni = 0; ni < 8; ni++)
            #pragma unroll
            for (int j = 0; j < 4; j++) c[mi][ni][j] = 0.f;

    gemm_mainloop(c, sbase, tid, lane, wm, wn, load_stage);

    const int quad = lane >> 2, qt = lane & 3;
    #pragma unroll
    for (int ni = 0; ni < 8; ni++) {
        const int o = colBase + wn * 64 + ni * 8 + qt * 2;
        const float b0 = bias[o], b1 = bias[o + 1];
        #pragma unroll
        for (int mi = 0; mi < 2; mi++) {
            #pragma unroll
            for (int half = 0; half < 2; half++) {
                const int m = rowBase + wm * 32 + mi * 16 + quad + half * 8;
                float2 v;
                v.x = c[mi][ni][half*2]     + b0;
                v.y = c[mi][ni][half*2 + 1] + b1;
                *(float2*)(out + (size_t)m * C_ + o) = v;
            }
        }
    }
}

// ---------------- flow passes: 8 halves/lane, 4 rows/warp ----------------
// lane: rgrp = lane>>3 (row in group of 4), lc8 = (lane&7)*8 (col base)
__global__ void passBB_kernel() {
    const int bh = blockIdx.x;
    const int rows0 = blockIdx.y * ROWS_PB;
    const int tid = threadIdx.x, lane = tid & 31, warp = tid >> 5;
    const int lc8 = (lane & 7) * 8, rgrp = lane >> 3;
    __shared__ float sv[64];
    __shared__ float partq[8][64], partk[8][64];
    if (tid < 64) sv[tid] = g_msum[bh * 64 + tid] + EPS_;
    __syncthreads();
    float ms[8];
    #pragma unroll
    for (int j = 0; j < 8; j++) ms[j] = sv[lc8 + j];
    const size_t base = (size_t)bh * N_ * D_;
    float aq[8], ak[8];
    #pragma unroll
    for (int j = 0; j < 8; j++) { aq[j] = 0.f; ak[j] = 0.f; }
    #pragma unroll
    for (int it = 0; it < 4; it++) {
        const int n = rows0 + it * 32 + warp * 4 + rgrp;
        float q[8], k[8];
        ld_h8(g_qh + base + (size_t)n * D_ + lc8, q);
        ld_h8(g_kh + base + (size_t)n * D_ + lc8, k);
        float dq = 0.f, dk = 0.f;
        #pragma unroll
        for (int j = 0; j < 8; j++) { dq += (q[j] + EPS_) * ms[j]; dk += (k[j] + EPS_) * ms[j]; }
        #pragma unroll
        for (int o = 4; o; o >>= 1) {
            dq += __shfl_xor_sync(0xffffffffu, dq, o);
            dk += __shfl_xor_sync(0xffffffffu, dk, o);
        }
        const float eq = 1.f / (dq + EPS_), ek = 1.f / (dk + EPS_);
        #pragma unroll
        for (int j = 0; j < 8; j++) { aq[j] += q[j] * eq; ak[j] += k[j] * ek; }
    }
    #pragma unroll
    for (int j = 0; j < 8; j++) {
        aq[j] += __shfl_xor_sync(0xffffffffu, aq[j], 8);
        aq[j] += __shfl_xor_sync(0xffffffffu, aq[j], 16);
        ak[j] += __shfl_xor_sync(0xffffffffu, ak[j], 8);
        ak[j] += __shfl_xor_sync(0xffffffffu, ak[j], 16);
    }
    if (rgrp == 0) {
        #pragma unroll
        for (int j = 0; j < 8; j++) { partq[warp][lc8+j] = aq[j]; partk[warp][lc8+j] = ak[j]; }
    }
    __syncthreads();
    if (tid < 64) {
        float s = 0.f;
        #pragma unroll
        for (int w = 0; w < 8; w++) s += partq[w][tid];
        atomicAdd(&g_qesum[bh * 64 + tid], s);
    } else if (tid < 128) {
        const int j = tid - 64;
        float s = 0.f;
        #pragma unroll
        for (int w = 0; w < 8; w++) s += partk[w][j];
        atomicAdd(&g_kesum[bh * 64 + j], s);
    }
}

__global__ void passC_kernel() {
    const int bh = blockIdx.x;
    const int rows0 = blockIdx.y * ROWS_PB;
    const int tid = threadIdx.x, lane = tid & 31, warp = tid >> 5;
    const int lc8 = (lane & 7) * 8, rgrp = lane >> 3;
    __shared__ float sq[64], sk[64];
    __shared__ float partq[8][64], partk[8][64];
    if (tid < 64) { sq[tid] = g_qesum[bh * 64 + tid] + EPS_; sk[tid] = g_kesum[bh * 64 + tid] + EPS_; }
    __syncthreads();
    float vq[8], vk[8];
    #pragma unroll
    for (int j = 0; j < 8; j++) { vq[j] = sq[lc8 + j]; vk[j] = sk[lc8 + j]; }
    const size_t base = (size_t)bh * N_ * D_;
    float aq[8], ak[8];
    #pragma unroll
    for (int j = 0; j < 8; j++) { aq[j] = 0.f; ak[j] = 0.f; }
    #pragma unroll
    for (int it = 0; it < 4; it++) {
        const int n = rows0 + it * 32 + warp * 4 + rgrp;
        float m[8];
        ld_h8(g_mh + base + (size_t)n * D_ + lc8, m);
        float dq = 0.f, dk = 0.f;
        #pragma unroll
        for (int j = 0; j < 8; j++) { dq += (m[j] + EPS_) * vq[j]; dk += (m[j] + EPS_) * vk[j]; }
        #pragma unroll
        for (int o = 4; o; o >>= 1) {
            dq += __shfl_xor_sync(0xffffffffu, dq, o);
            dk += __shfl_xor_sync(0xffffffffu, dk, o);
        }
        const float tq = sigm(dq + EPS_), tk = sigm(dk + EPS_);
        __half* qp = g_qh + base + (size_t)n * D_ + lc8;
        __half* kp = g_kh + base + (size_t)n * D_ + lc8;
        float q[8], k[8];
        ld_h8(qp, q); ld_h8(kp, k);
        #pragma unroll
        for (int j = 0; j < 8; j++) {
            q[j] *= (1.f + m[j] * tq);
            k[j] *= (1.f + m[j] * tk);
            aq[j] += q[j]; ak[j] += k[j];
        }
        st_h8(qp, q); st_h8(kp, k);
    }
    #pragma unroll
    for (int j = 0; j < 8; j++) {
        aq[j] += __shfl_xor_sync(0xffffffffu, aq[j], 8);
        aq[j] += __shfl_xor_sync(0xffffffffu, aq[j], 16);
        ak[j] += __shfl_xor_sync(0xffffffffu, ak[j], 8);
        ak[j] += __shfl_xor_sync(0xffffffffu, ak[j], 16);
    }
    if (rgrp == 0) {
        #pragma unroll
        for (int j = 0; j < 8; j++) { partq[warp][lc8+j] = aq[j]; partk[warp][lc8+j] = ak[j]; }
    }
    __syncthreads();
    if (tid < 64) {
        float s = 0.f;
        #pragma unroll
        for (int w = 0; w < 8; w++) s += partq[w][tid];
        atomicAdd(&g_qhsum[bh * 64 + tid], s);
    } else if (tid < 128) {
        const int j = tid - 64;
        float s = 0.f;
        #pragma unroll
        for (int w = 0; w < 8; w++) s += partk[w][j];
        atomicAdd(&g_khsum[bh * 64 + j], s);
    }
}

__global__ void passE_kernel() {
    const int bh = blockIdx.x;
    const int rows0 = blockIdx.y * ROWS_PB;
    const int tid = threadIdx.x, lane = tid & 31, warp = tid >> 5;
    const int lc8 = (lane & 7) * 8, rgrp = lane >> 3;
    __shared__ float skh[64], sqh[64];
    __shared__ float partq[8][64], partk[8][64];
    if (tid < 64) { skh[tid] = g_khsum[bh * 64 + tid] + EPS_; sqh[tid] = g_qhsum[bh * 64 + tid] + EPS_; }
    __syncthreads();
    float vkh[8], vqh[8];
    #pragma unroll
    for (int j = 0; j < 8; j++) { vkh[j] = skh[lc8 + j]; vqh[j] = sqh[lc8 + j]; }
    const size_t base = (size_t)bh * N_ * D_;
    float aq[8], ak[8];
    #pragma unroll
    for (int j = 0; j < 8; j++) { aq[j] = 0.f; ak[j] = 0.f; }
    #pragma unroll
    for (int it = 0; it < 4; it++) {
        const int n = rows0 + it * 32 + warp * 4 + rgrp;
        float q[8], k[8];
        ld_h8(g_qh + base + (size_t)n * D_ + lc8, q);
        ld_h8(g_kh + base + (size_t)n * D_ + lc8, k);
        float di = 0.f, dz = 0.f;
        #pragma unroll
        for (int j = 0; j < 8; j++) { di += (q[j] + EPS_) * vkh[j]; dz += (k[j] + EPS_) * vqh[j]; }
        #pragma unroll
        for (int o = 4; o; o >>= 1) {
            di += __shfl_xor_sync(0xffffffffu, di, o);
            dz += __shfl_xor_sync(0xffffffffu, dz, o);
        }
        const float si = 1.f / (di + EPS_), so = 1.f / (dz + EPS_);
        if ((lane & 7) == 0) g_si[bh * N_ + n] = si;
        #pragma unroll
        for (int j = 0; j < 8; j++) { aq[j] += q[j] * si; ak[j] += k[j] * so; }
    }
    #pragma unroll
    for (int j = 0; j < 8; j++) {
        aq[j] += __shfl_xor_sync(0xffffffffu, aq[j], 8);
        aq[j] += __shfl_xor_sync(0xffffffffu, aq[j], 16);
        ak[j] += __shfl_xor_sync(0xffffffffu, ak[j], 8);
        ak[j] += __shfl_xor_sync(0xffffffffu, ak[j], 16);
    }
    if (rgrp == 0) {
        #pragma unroll
        for (int j = 0; j < 8; j++) { partq[warp][lc8+j] = aq[j]; partk[warp][lc8+j] = ak[j]; }
    }
    __syncthreads();
    if (tid < 64) {
        float s = 0.f;
        #pragma unroll
        for (int w = 0; w < 8; w++) s += partq[w][tid];
        atomicAdd(&g_qsisum[bh * 64 + tid], s);
    } else if (tid < 128) {
        const int j = tid - 64;
        float s = 0.f;
        #pragma unroll
        for (int w = 0; w < 8; w++) s += partk[w][j];
        atomicAdd(&g_ksosum[bh * 64 + j], s);
    }
}

// ---------------- fused passF + kvagg (fp16 loads -> fp32 smem) ----------------
#define AGG_SPLIT 8
__global__ __launch_bounds__(256)
void passFG_kernel() {
    const int bh = blockIdx.x;
    const int rows0 = blockIdx.y * (N_ / AGG_SPLIT);
    const int tid = threadIdx.x, lane = tid & 31, warp = tid >> 5;
    const int tx = tid & 15, ty = tid >> 4;
    __shared__ float skso[64], sqsi[64];
    __shared__ __align__(16) float sk[16][64];
    __shared__ __align__(16) float sv[16][64];
    __shared__ float escs[16];
    if (tid < 64) { skso[tid] = g_ksosum[bh * 64 + tid] + EPS_; sqsi[tid] = g_qsisum[bh * 64 + tid] + EPS_; }
    __syncthreads();
    const float a0 = skso[lane*2], a1 = skso[lane*2+1];
    const float b0 = sqsi[lane*2], b1 = sqsi[lane*2+1];
    const size_t base = (size_t)bh * N_ * D_;
    float acc[4][4];
    #pragma unroll
    for (int i = 0; i < 4; i++)
        #pragma unroll
        for (int j = 0; j < 4; j++) acc[i][j] = 0.f;
    float sumexp_loc = 0.f;

    for (int c = 0; c < N_ / AGG_SPLIT; c += 16) {
        #pragma unroll
        for (int i = 0; i < 2; i++) {
            const int li = tid + i * 256;          // 0..511 half2 units
            const int r = li >> 5, d2 = li & 31;
            const int n = rows0 + c + r;
            float2 fk = __half22float2(((const __half2*)(g_kh + base + (size_t)n * D_))[d2]);
            float2 fv = __half22float2(((const __half2*)(g_vh + base + (size_t)n * D_))[d2]);
            sk[r][d2*2] = fk.x; sk[r][d2*2+1] = fk.y;
            sv[r][d2*2] = fv.x; sv[r][d2*2+1] = fv.y;
        }
        __syncthreads();
        #pragma unroll
        for (int rr = 0; rr < 2; rr++) {
            const int r = warp * 2 + rr;
            const int n = rows0 + c + r;
            float2 q2 = __half22float2(*(const __half2*)(g_qh + base + (size_t)n * D_ + lane * 2));
            const float kx = sk[r][lane*2], ky = sk[r][lane*2+1];
            float dq = (q2.x + EPS_) * a0 + (q2.y + EPS_) * a1;
            float dk = (kx + EPS_) * b0 + (ky + EPS_) * b1;
            #pragma unroll
            for (int o = 16; o; o >>= 1) {
                dq += __shfl_xor_sync(0xffffffffu, dq, o);
                dk += __shfl_xor_sync(0xffffffffu, dk, o);
            }
            if (lane == 0) {
                const float csink = dq + EPS_;
                float cs = fminf(fmaxf(dk + EPS_, -1.f), 1.f);
                const float e = __expf(cs);
                escs[r] = e;
                sumexp_loc += e;
                const int idx = bh * N_ + n;
                g_ssink[idx] = g_si[idx] * sigm(csink);
            }
        }
        __syncthreads();
        #pragma unroll
        for (int r = 0; r < 16; r++) {
            const float es = escs[r];
            const float4 kk = ((const float4*)sk[r])[ty];
            float4 vv = ((const float4*)sv[r])[tx];
            vv.x *= es; vv.y *= es; vv.z *= es; vv.w *= es;
            acc[0][0] += kk.x*vv.x; acc[0][1] += kk.x*vv.y; acc[0][2] += kk.x*vv.z; acc[0][3] += kk.x*vv.w;
            acc[1][0] += kk.y*vv.x; acc[1][1] += kk.y*vv.y; acc[1][2] += kk.y*vv.z; acc[1][3] += kk.y*vv.w;
            acc[2][0] += kk.z*vv.x; acc[2][1] += kk.z*vv.y; acc[2][2] += kk.z*vv.z; acc[2][3] += kk.z*vv.w;
            acc[3][0] += kk.w*vv.x; acc[3][1] += kk.w*vv.y; acc[3][2] += kk.w*vv.z; acc[3][3] += kk.w*vv.w;
        }
        __syncthreads();
    }
    #pragma unroll
    for (int i = 0; i < 4; i++)
        #pragma unroll
        for (int j = 0; j < 4; j++)
            atomicAdd(&g_agg[bh * 4096 + (ty * 4 + i) * 64 + tx * 4 + j], acc[i][j]);
    if (lane == 0) atomicAdd(&g_sumexp[bh], sumexp_loc);
}

// ---------------- xout (fp16 qh loads) ----------------
__global__ __launch_bounds__(256)
void xout_kernel() {
    const int bh = blockIdx.x;
    const int b = bh / H_, h = bh % H_;
    const int rows0 = blockIdx.y * 64;
    const int tid = threadIdx.x;
    __shared__ __align__(16) float sagg[64][64];
    __shared__ __align__(16) float sq[64][65];
    const float scl = (float)N_ / g_sumexp[bh];
    #pragma unroll
    for (int i = 0; i < 16; i++) {
        const int li = tid + i * 256;
        sagg[li >> 6][li & 63] = g_agg[bh * 4096 + li];
    }
    const size_t base = (size_t)bh * N_ * D_ + (size_t)rows0 * D_;
    #pragma unroll
    for (int i = 0; i < 8; i++) {
        const int li = tid + i * 256;              // 0..2047 half2 units
        const int r = li >> 5, d2 = li & 31;
        float2 f = __half22float2(((const __half2*)(g_qh + base + (size_t)r * D_))[d2]);
        sq[r][d2*2] = f.x; sq[r][d2*2+1] = f.y;
    }
    __syncthreads();
    const int r = tid >> 2, ch = tid & 3;
    float acc[16];
    #pragma unroll
    for (int j = 0; j < 16; j++) acc[j] = 0.f;
    #pragma unroll 8
    for (int d = 0; d < 64; d++) {
        const float qv = sq[r][d];
        const float4* ag = (const float4*)(&sagg[d][ch * 16]);
        #pragma unroll
        for (int j4 = 0; j4 < 4; j4++) {
            float4 av = ag[j4];
            acc[j4*4+0] += qv * av.x; acc[j4*4+1] += qv * av.y;
            acc[j4*4+2] += qv * av.z; acc[j4*4+3] += qv * av.w;
        }
    }
    const int n = rows0 + r;
    const float s = g_ssink[bh * N_ + n] * scl;
    __half* xr = g_ah + ((size_t)b * N_ + n) * C_ + h * 64 + ch * 16;
    uint32_t u[8];
    #pragma unroll
    for (int j = 0; j < 8; j++) {
        __half2 hh = __floats2half2_rn(acc[2*j] * s, acc[2*j+1] * s);
        u[j] = *(uint32_t*)&hh;
    }
    ((uint4*)xr)[0] = make_uint4(u[0], u[1], u[2], u[3]);
    ((uint4*)xr)[1] = make_uint4(u[4], u[5], u[6], u[7]);
}

// ---------------- launch ----------------
extern "C" void kernel_launch(void* const* d_in, const int* in_sizes, int n_in,
                              void* d_out, int out_size) {
    const float* q      = (const float*)d_in[0];
    const float* kv     = (const float*)d_in[1];
    const float* motion = (const float*)d_in[2];
    const float* Wq = (const float*)d_in[3];  const float* bq = (const float*)d_in[4];
    const float* Wk = (const float*)d_in[5];  const float* bk = (const float*)d_in[6];
    const float* Wv = (const float*)d_in[7];  const float* bv = (const float*)d_in[8];
    const float* Wm = (const float*)d_in[9];  const float* bm = (const float*)d_in[10];
    const float* Wo = (const float*)d_in[11]; const float* bo = (const float*)d_in[12];
    float* out = (float*)d_out;

    __half *p_qh, *p_kh, *p_vh, *p_mh, *p_ah, *p_wh;
    cudaGetSymbolAddress((void**)&p_qh, g_qh);
    cudaGetSymbolAddress((void**)&p_kh, g_kh);
    cudaGetSymbolAddress((void**)&p_vh, g_vh);
    cudaGetSymbolAddress((void**)&p_mh, g_mh);
    cudaGetSymbolAddress((void**)&p_ah, g_ah);
    cudaGetSymbolAddress((void**)&p_wh, g_wh);

    cudaFuncSetAttribute(gemm_proj, cudaFuncAttributeMaxDynamicSharedMemorySize, GEMM_SMEM);
    cudaFuncSetAttribute(gemm_out,  cudaFuncAttributeMaxDynamicSharedMemorySize, GEMM_SMEM);

    const dim3 gProj(C_ / 128, M_ / 128, 4);
    const dim3 gOut(C_ / 128, M_ / 128);
    const dim3 gRed(BH_, SPLIT_);
    const int actN4 = M_ * C_ / 4;
    const int wN4   = C_ * C_ / 4;
    const int actBlk = (actN4 + 255) / 256;
    const int wBlk   = (wN4 + 255) / 256;
    const size_t WS = (size_t)C_ * C_;

    zero_kernel<<<(BH_*D_*D_ + 255) / 256, 256>>>();
    f2h_w5_kernel<<<dim3(wBlk, 5), 256>>>(Wq, Wk, Wv, Wm, Wo, p_wh);
    f2h_acts_kernel<<<dim3(actBlk, 3), 256>>>(q, kv, motion, p_ah);

    gemm_proj<<<gProj, 256, GEMM_SMEM>>>(p_ah, p_wh, bq, bk, bv, bm, p_qh, p_kh, p_vh, p_mh);

    passBB_kernel<<<gRed, 256>>>();
    passC_kernel<<<gRed, 256>>>();
    passE_kernel<<<gRed, 256>>>();
    passFG_kernel<<<dim3(BH_, AGG_SPLIT), 256>>>();
    xout_kernel<<<dim3(BH_, N_ / 64), 256>>>();

    gemm_out<<<gOut, 256, GEMM_SMEM>>>(p_ah, p_wh + 4*WS, bo, out);
}

// round 17
// speedup vs baseline: 1.1624x; 1.0178x over previous
#include <cuda_runtime.h>
#include <cuda_fp16.h>
#include <cstdint>
#include <math.h>

#define B_ 4
#define N_ 4096
#define C_ 768
#define H_ 12
#define D_ 64
#define BH_ 48
#define M_ (B_*N_)
#define EPS_ 1e-6f
#define SPLIT_ 32
#define ROWS_PB (N_/SPLIT_)   // 128

// ---- mma.sync GEMM config (R12/R14 best) ----
#define KDIM 768
#define KCHUNK 64
#define NCHUNKS 12
#define ROWH 72
#define ROWB (ROWH*2)
#define TILE_BYTES (128*ROWB)
#define STAGE_BYTES (2*TILE_BYTES)
#define GEMM_SMEM (3*STAGE_BYTES)    // 110592

// ---------------- scratch (flow intermediates fp16) ----------------
__device__ __half g_qh[BH_*N_*D_];
__device__ __half g_kh[BH_*N_*D_];
__device__ __half g_vh[BH_*N_*D_];
__device__ __half g_mh[BH_*N_*D_];
__device__ float g_msum[BH_*D_];
__device__ float g_qesum[BH_*D_];
__device__ float g_kesum[BH_*D_];
__device__ float g_qhsum[BH_*D_];
__device__ float g_khsum[BH_*D_];
__device__ float g_qsisum[BH_*D_];
__device__ float g_ksosum[BH_*D_];
__device__ float g_si[BH_*N_];
__device__ float g_ssink[BH_*N_];
__device__ float g_sumexp[BH_];
__device__ float g_agg[BH_*D_*D_];
__device__ __half g_ah[(size_t)3*M_*C_];
__device__ __half g_wh[(size_t)5*C_*C_];

__device__ __forceinline__ float sigm(float x) { return 1.f / (1.f + __expf(-x)); }

__device__ __forceinline__ uint32_t smem_u32(const void* p) {
    uint32_t a;
    asm("{ .reg .u64 t; cvta.to.shared.u64 t, %1; cvt.u32.u64 %0, t; }" : "=r"(a) : "l"(p));
    return a;
}
__device__ __forceinline__ void cpasync16(uint32_t dst, const void* src) {
    asm volatile("cp.async.cg.shared.global [%0], [%1], 16;" :: "r"(dst), "l"(src) : "memory");
}
#define LDSM4(r0,r1,r2,r3,addr) \
    asm volatile("ldmatrix.sync.aligned.m8n8.x4.shared.b16 {%0,%1,%2,%3}, [%4];" \
        : "=r"(r0),"=r"(r1),"=r"(r2),"=r"(r3) : "r"(addr))
#define MMA16816(c, a, b0, b1) \
    asm volatile("mma.sync.aligned.m16n8k16.row.col.f32.f16.f16.f32 " \
        "{%0,%1,%2,%3}, {%4,%5,%6,%7}, {%8,%9}, {%0,%1,%2,%3};" \
        : "+f"((c)[0]),"+f"((c)[1]),"+f"((c)[2]),"+f"((c)[3]) \
        : "r"((a)[0]),"r"((a)[1]),"r"((a)[2]),"r"((a)[3]),"r"(b0),"r"(b1))

// unpack uint4 (8 halves) -> 8 floats
__device__ __forceinline__ void h8_unpack(uint4 u, float* f) {
    float2 a = __half22float2(*(__half2*)&u.x);
    float2 b = __half22float2(*(__half2*)&u.y);
    float2 c = __half22float2(*(__half2*)&u.z);
    float2 d = __half22float2(*(__half2*)&u.w);
    f[0]=a.x; f[1]=a.y; f[2]=b.x; f[3]=b.y; f[4]=c.x; f[5]=c.y; f[6]=d.x; f[7]=d.y;
}
__device__ __forceinline__ void st_h8(__half* p, const float* f) {
    uint4 u;
    __half2 h0 = __floats2half2_rn(f[0], f[1]);
    __half2 h1 = __floats2half2_rn(f[2], f[3]);
    __half2 h2 = __floats2half2_rn(f[4], f[5]);
    __half2 h3 = __floats2half2_rn(f[6], f[7]);
    u.x = *(uint32_t*)&h0; u.y = *(uint32_t*)&h1; u.z = *(uint32_t*)&h2; u.w = *(uint32_t*)&h3;
    *(uint4*)p = u;
}

// ---------------- zero accumulators ----------------
__global__ void zero_kernel() {
    int i = blockIdx.x * blockDim.x + threadIdx.x;
    if (i < BH_*D_) {
        g_msum[i] = 0.f; g_qesum[i] = 0.f; g_kesum[i] = 0.f;
        g_qhsum[i] = 0.f; g_khsum[i] = 0.f; g_qsisum[i] = 0.f; g_ksosum[i] = 0.f;
    }
    if (i < BH_) g_sumexp[i] = 0.f;
    if (i < BH_*D_*D_) g_agg[i] = 0.f;
}

// ---------------- fp32 -> fp16 ----------------
__global__ void f2h_acts_kernel(const float* a0, const float* a1, const float* a2,
                                __half* __restrict__ dst) {
    const int n4 = M_ * C_ / 4;
    int i = blockIdx.x * 256 + threadIdx.x;
    if (i >= n4) return;
    const float* src = blockIdx.y == 0 ? a0 : blockIdx.y == 1 ? a1 : a2;
    float4 v = ((const float4*)src)[i];
    __half* d = dst + (size_t)blockIdx.y * M_ * C_;
    ((__half2*)d)[i*2]   = __floats2half2_rn(v.x, v.y);
    ((__half2*)d)[i*2+1] = __floats2half2_rn(v.z, v.w);
}
__global__ void f2h_w5_kernel(const float* w0, const float* w1, const float* w2,
                              const float* w3, const float* w4, __half* __restrict__ dst) {
    const int n4 = C_ * C_ / 4;
    int i = blockIdx.x * 256 + threadIdx.x;
    if (i >= n4) return;
    const float* src = blockIdx.y == 0 ? w0 : blockIdx.y == 1 ? w1 : blockIdx.y == 2 ? w2
                     : blockIdx.y == 3 ? w3 : w4;
    float4 v = ((const float4*)src)[i];
    __half* d = dst + (size_t)blockIdx.y * C_ * C_;
    ((__half2*)d)[i*2]   = __floats2half2_rn(v.x, v.y);
    ((__half2*)d)[i*2+1] = __floats2half2_rn(v.z, v.w);
}

// ---------------- GEMM mainloop (R12/R14) ----------------
template<typename LoaderT>
__device__ __forceinline__ void gemm_mainloop(
    float c[2][8][4], const uint32_t sbase, const int tid, const int lane,
    const int wm, const int wn, LoaderT load_stage) {
    const int lrow = lane & 15;
    const int lkof = (lane >> 4) * 8;
    const uint32_t rowOffA = (wm * 32 + lrow) * ROWB;

    uint32_t af[2][8], bf[2][16];

    for (int kt = 0; kt < NCHUNKS; kt++) {
        if (kt + 1 < NCHUNKS) asm volatile("cp.async.wait_group 1;" ::: "memory");
        else                  asm volatile("cp.async.wait_group 0;" ::: "memory");
        __syncthreads();
        const int s = kt % 3;
        const uint32_t aBase = sbase + s * STAGE_BYTES;
        const uint32_t bBase = aBase + TILE_BYTES;
        if (kt + 2 < NCHUNKS) load_stage((kt + 2) % 3, kt + 2);

        {
            const uint32_t kb = lkof * 2;
            const uint32_t aA = aBase + rowOffA + kb;
            LDSM4(af[0][0], af[0][1], af[0][2], af[0][3], aA);
            LDSM4(af[0][4], af[0][5], af[0][6], af[0][7], aA + 16 * ROWB);
            #pragma unroll
            for (int nb = 0; nb < 4; nb++) {
                const uint32_t aB = bBase + (wn * 64 + nb * 16 + lrow) * ROWB + kb;
                LDSM4(bf[0][nb*4+0], bf[0][nb*4+1], bf[0][nb*4+2], bf[0][nb*4+3], aB);
            }
        }
        #pragma unroll
        for (int ks = 0; ks < 4; ks++) {
            const int cur = ks & 1, nxt = cur ^ 1;
            if (ks < 3) {
                const uint32_t kb = ((ks + 1) * 16 + lkof) * 2;
                const uint32_t aA = aBase + rowOffA + kb;
                LDSM4(af[nxt][0], af[nxt][1], af[nxt][2], af[nxt][3], aA);
                LDSM4(af[nxt][4], af[nxt][5], af[nxt][6], af[nxt][7], aA + 16 * ROWB);
                #pragma unroll
                for (int nb = 0; nb < 4; nb++) {
                    const uint32_t aB = bBase + (wn * 64 + nb * 16 + lrow) * ROWB + kb;
                    LDSM4(bf[nxt][nb*4+0], bf[nxt][nb*4+1], bf[nxt][nb*4+2], bf[nxt][nb*4+3], aB);
                }
            }
            #pragma unroll
            for (int nb = 0; nb < 4; nb++) {
                MMA16816(c[0][2*nb],   af[cur],     bf[cur][nb*4+0], bf[cur][nb*4+2]);
                MMA16816(c[1][2*nb],   af[cur] + 4, bf[cur][nb*4+0], bf[cur][nb*4+2]);
                MMA16816(c[0][2*nb+1], af[cur],     bf[cur][nb*4+1], bf[cur][nb*4+3]);
                MMA16816(c[1][2*nb+1], af[cur] + 4, bf[cur][nb*4+1], bf[cur][nb*4+3]);
            }
        }
    }
}

// ---------------- merged projection GEMM (fp16 head-layout epilogue) ----------------
__global__ void __launch_bounds__(256, 2)
gemm_proj(const __half* __restrict__ Aall, const __half* __restrict__ Wall,
          const float* __restrict__ bq, const float* __restrict__ bk,
          const float* __restrict__ bv, const float* __restrict__ bm,
          __half* __restrict__ oq, __half* __restrict__ ok,
          __half* __restrict__ ov, __half* __restrict__ om) {
    extern __shared__ char smem[];
    const uint32_t sbase = smem_u32(smem);
    const int tid = threadIdx.x;
    const int lane = tid & 31, w = tid >> 5;
    const int wm = w & 3, wn = w >> 2;
    const int z = blockIdx.z;
    const int rowBase = blockIdx.y * 128, colBase = blockIdx.x * 128;
    const int aslot = (z == 0) ? 0 : (z == 3) ? 2 : 1;
    const __half* Ab = Aall + (size_t)aslot * M_ * C_ + (size_t)rowBase * KDIM;
    const __half* Wb = Wall + (size_t)z * C_ * C_ + (size_t)colBase * KDIM;
    const float* bias = (z == 0) ? bq : (z == 1) ? bk : (z == 2) ? bv : bm;
    __half* out = (z == 0) ? oq : (z == 1) ? ok : (z == 2) ? ov : om;
    const bool doSig = (z != 2);
    const bool doCsum = (z == 3);

    auto load_stage = [&](int s, int kt) {
        const int kofs = kt * KCHUNK;
        const uint32_t dstA = sbase + s * STAGE_BYTES;
        const uint32_t dstB = dstA + TILE_BYTES;
        #pragma unroll
        for (int i = 0; i < 8; i++) {
            const int idx = tid + i * 256;
            const int r = (idx & 1023) >> 3;
            const int c = idx & 7;
            const __half* src = (idx < 1024 ? Ab : Wb) + (size_t)r * KDIM + kofs + c * 8;
            const uint32_t dst = (idx < 1024 ? dstA : dstB) + r * ROWB + c * 16;
            cpasync16(dst, src);
        }
        asm volatile("cp.async.commit_group;" ::: "memory");
    };

    load_stage(0, 0); load_stage(1, 1);

    float c[2][8][4];
    #pragma unroll
    for (int mi = 0; mi < 2; mi++)
        #pragma unroll
        for (int ni = 0; ni < 8; ni++)
            #pragma unroll
            for (int j = 0; j < 4; j++) c[mi][ni][j] = 0.f;

    gemm_mainloop(c, sbase, tid, lane, wm, wn, load_stage);

    float* colacc = (float*)smem;
    if (doCsum) {
        __syncthreads();
        if (tid < 128) colacc[tid] = 0.f;
        __syncthreads();
    }
    const int quad = lane >> 2, qt = lane & 3;
    #pragma unroll
    for (int ni = 0; ni < 8; ni++) {
        const int o = colBase + wn * 64 + ni * 8 + qt * 2;
        const float b0 = bias[o], b1 = bias[o + 1];
        float sx = 0.f, sy = 0.f;
        #pragma unroll
        for (int mi = 0; mi < 2; mi++) {
            #pragma unroll
            for (int half = 0; half < 2; half++) {
                const int m = rowBase + wm * 32 + mi * 16 + quad + half * 8;
                float vx = c[mi][ni][half*2]     + b0;
                float vy = c[mi][ni][half*2 + 1] + b1;
                if (doSig) { vx = sigm(vx); vy = sigm(vy); }
                sx += vx; sy += vy;
                const int bb = m >> 12, n = m & (N_ - 1);
                __half2 hv = __floats2half2_rn(vx, vy);
                *(__half2*)(out + (((size_t)(bb * H_ + (o >> 6))) * N_ + n) * D_ + (o & 63)) = hv;
            }
        }
        if (doCsum) {
            const int lo = wn * 64 + ni * 8 + qt * 2;
            atomicAdd(&colacc[lo], sx);
            atomicAdd(&colacc[lo + 1], sy);
        }
    }
    if (doCsum) {
        __syncthreads();
        if (tid < 128) {
            const int b = rowBase >> 12;
            const int o = colBase + tid;
            atomicAdd(&g_msum[(b * H_ + (o >> 6)) * D_ + (o & 63)], colacc[tid]);
        }
    }
}

// ---------------- output GEMM ----------------
__global__ void __launch_bounds__(256, 2)
gemm_out(const __half* __restrict__ A, const __half* __restrict__ W,
         const float* __restrict__ bias, float* __restrict__ out) {
    extern __shared__ char smem[];
    const uint32_t sbase = smem_u32(smem);
    const int tid = threadIdx.x;
    const int lane = tid & 31, w = tid >> 5;
    const int wm = w & 3, wn = w >> 2;
    const int rowBase = blockIdx.y * 128, colBase = blockIdx.x * 128;
    const __half* Ab = A + (size_t)rowBase * KDIM;
    const __half* Wb = W + (size_t)colBase * KDIM;

    auto load_stage = [&](int s, int kt) {
        const int kofs = kt * KCHUNK;
        const uint32_t dstA = sbase + s * STAGE_BYTES;
        const uint32_t dstB = dstA + TILE_BYTES;
        #pragma unroll
        for (int i = 0; i < 8; i++) {
            const int idx = tid + i * 256;
            const int r = (idx & 1023) >> 3;
            const int c = idx & 7;
            const __half* src = (idx < 1024 ? Ab : Wb) + (size_t)r * KDIM + kofs + c * 8;
            const uint32_t dst = (idx < 1024 ? dstA : dstB) + r * ROWB + c * 16;
            cpasync16(dst, src);
        }
        asm volatile("cp.async.commit_group;" ::: "memory");
    };

    load_stage(0, 0); load_stage(1, 1);

    float c[2][8][4];
    #pragma unroll
    for (int mi = 0; mi < 2; mi++)
        #pragma unroll
        for (int ni = 0; ni < 8; ni++)
            #pragma unroll
            for (int j = 0; j < 4; j++) c[mi][ni][j] = 0.f;

    gemm_mainloop(c, sbase, tid, lane, wm, wn, load_stage);

    const int quad = lane >> 2, qt = lane & 3;
    #pragma unroll
    for (int ni = 0; ni < 8; ni++) {
        const int o = colBase + wn * 64 + ni * 8 + qt * 2;
        const float b0 = bias[o], b1 = bias[o + 1];
        #pragma unroll
        for (int mi = 0; mi < 2; mi++) {
            #pragma unroll
            for (int half = 0; half < 2; half++) {
                const int m = rowBase + wm * 32 + mi * 16 + quad + half * 8;
                float2 v;
                v.x = c[mi][ni][half*2]     + b0;
                v.y = c[mi][ni][half*2 + 1] + b1;
                *(float2*)(out + (size_t)m * C_ + o) = v;
            }
        }
    }
}

// ---------------- flow passes: batched-MLP (all 4 iters' loads in flight) ----------------
// lane: rgrp = lane>>3 (row in group of 4), lc8 = (lane&7)*8
__global__ void passBB_kernel() {
    const int bh = blockIdx.x;
    const int rows0 = blockIdx.y * ROWS_PB;
    const int tid = threadIdx.x, lane = tid & 31, warp = tid >> 5;
    const int lc8 = (lane & 7) * 8, rgrp = lane >> 3;
    __shared__ float sv[64];
    __shared__ float partq[8][64], partk[8][64];
    if (tid < 64) sv[tid] = g_msum[bh * 64 + tid] + EPS_;
    __syncthreads();
    float ms[8];
    #pragma unroll
    for (int j = 0; j < 8; j++) ms[j] = sv[lc8 + j];
    const size_t base = (size_t)bh * N_ * D_;

    uint4 rq[4], rk[4];
    #pragma unroll
    for (int it = 0; it < 4; it++) {
        const int n = rows0 + it * 32 + warp * 4 + rgrp;
        rq[it] = *(const uint4*)(g_qh + base + (size_t)n * D_ + lc8);
        rk[it] = *(const uint4*)(g_kh + base + (size_t)n * D_ + lc8);
    }
    float aq[8], ak[8];
    #pragma unroll
    for (int j = 0; j < 8; j++) { aq[j] = 0.f; ak[j] = 0.f; }
    #pragma unroll
    for (int it = 0; it < 4; it++) {
        float q[8], k[8];
        h8_unpack(rq[it], q); h8_unpack(rk[it], k);
        float dq = 0.f, dk = 0.f;
        #pragma unroll
        for (int j = 0; j < 8; j++) { dq += (q[j] + EPS_) * ms[j]; dk += (k[j] + EPS_) * ms[j]; }
        #pragma unroll
        for (int o = 4; o; o >>= 1) {
            dq += __shfl_xor_sync(0xffffffffu, dq, o);
            dk += __shfl_xor_sync(0xffffffffu, dk, o);
        }
        const float eq = 1.f / (dq + EPS_), ek = 1.f / (dk + EPS_);
        #pragma unroll
        for (int j = 0; j < 8; j++) { aq[j] += q[j] * eq; ak[j] += k[j] * ek; }
    }
    #pragma unroll
    for (int j = 0; j < 8; j++) {
        aq[j] += __shfl_xor_sync(0xffffffffu, aq[j], 8);
        aq[j] += __shfl_xor_sync(0xffffffffu, aq[j], 16);
        ak[j] += __shfl_xor_sync(0xffffffffu, ak[j], 8);
        ak[j] += __shfl_xor_sync(0xffffffffu, ak[j], 16);
    }
    if (rgrp == 0) {
        #pragma unroll
        for (int j = 0; j < 8; j++) { partq[warp][lc8+j] = aq[j]; partk[warp][lc8+j] = ak[j]; }
    }
    __syncthreads();
    if (tid < 64) {
        float s = 0.f;
        #pragma unroll
        for (int w = 0; w < 8; w++) s += partq[w][tid];
        atomicAdd(&g_qesum[bh * 64 + tid], s);
    } else if (tid < 128) {
        const int j = tid - 64;
        float s = 0.f;
        #pragma unroll
        for (int w = 0; w < 8; w++) s += partk[w][j];
        atomicAdd(&g_kesum[bh * 64 + j], s);
    }
}

__global__ void passC_kernel() {
    const int bh = blockIdx.x;
    const int rows0 = blockIdx.y * ROWS_PB;
    const int tid = threadIdx.x, lane = tid & 31, warp = tid >> 5;
    const int lc8 = (lane & 7) * 8, rgrp = lane >> 3;
    __shared__ float sq[64], sk[64];
    __shared__ float partq[8][64], partk[8][64];
    if (tid < 64) { sq[tid] = g_qesum[bh * 64 + tid] + EPS_; sk[tid] = g_kesum[bh * 64 + tid] + EPS_; }
    __syncthreads();
    float vq[8], vk[8];
    #pragma unroll
    for (int j = 0; j < 8; j++) { vq[j] = sq[lc8 + j]; vk[j] = sk[lc8 + j]; }
    const size_t base = (size_t)bh * N_ * D_;

    uint4 rm[4], rq[4], rk[4];
    #pragma unroll
    for (int it = 0; it < 4; it++) {
        const int n = rows0 + it * 32 + warp * 4 + rgrp;
        rm[it] = *(const uint4*)(g_mh + base + (size_t)n * D_ + lc8);
        rq[it] = *(const uint4*)(g_qh + base + (size_t)n * D_ + lc8);
        rk[it] = *(const uint4*)(g_kh + base + (size_t)n * D_ + lc8);
    }
    float aq[8], ak[8];
    #pragma unroll
    for (int j = 0; j < 8; j++) { aq[j] = 0.f; ak[j] = 0.f; }
    #pragma unroll
    for (int it = 0; it < 4; it++) {
        const int n = rows0 + it * 32 + warp * 4 + rgrp;
        float m[8], q[8], k[8];
        h8_unpack(rm[it], m);
        float dq = 0.f, dk = 0.f;
        #pragma unroll
        for (int j = 0; j < 8; j++) { dq += (m[j] + EPS_) * vq[j]; dk += (m[j] + EPS_) * vk[j]; }
        #pragma unroll
        for (int o = 4; o; o >>= 1) {
            dq += __shfl_xor_sync(0xffffffffu, dq, o);
            dk += __shfl_xor_sync(0xffffffffu, dk, o);
        }
        const float tq = sigm(dq + EPS_), tk = sigm(dk + EPS_);
        h8_unpack(rq[it], q); h8_unpack(rk[it], k);
        #pragma unroll
        for (int j = 0; j < 8; j++) {
            q[j] *= (1.f + m[j] * tq);
            k[j] *= (1.f + m[j] * tk);
            aq[j] += q[j]; ak[j] += k[j];
        }
        st_h8(g_qh + base + (size_t)n * D_ + lc8, q);
        st_h8(g_kh + base + (size_t)n * D_ + lc8, k);
    }
    #pragma unroll
    for (int j = 0; j < 8; j++) {
        aq[j] += __shfl_xor_sync(0xffffffffu, aq[j], 8);
        aq[j] += __shfl_xor_sync(0xffffffffu, aq[j], 16);
        ak[j] += __shfl_xor_sync(0xffffffffu, ak[j], 8);
        ak[j] += __shfl_xor_sync(0xffffffffu, ak[j], 16);
    }
    if (rgrp == 0) {
        #pragma unroll
        for (int j = 0; j < 8; j++) { partq[warp][lc8+j] = aq[j]; partk[warp][lc8+j] = ak[j]; }
    }
    __syncthreads();
    if (tid < 64) {
        float s = 0.f;
        #pragma unroll
        for (int w = 0; w < 8; w++) s += partq[w][tid];
        atomicAdd(&g_qhsum[bh * 64 + tid], s);
    } else if (tid < 128) {
        const int j = tid - 64;
        float s = 0.f;
        #pragma unroll
        for (int w = 0; w < 8; w++) s += partk[w][j];
        atomicAdd(&g_khsum[bh * 64 + j], s);
    }
}

__global__ void passE_kernel() {
    const int bh = blockIdx.x;
    const int rows0 = blockIdx.y * ROWS_PB;
    const int tid = threadIdx.x, lane = tid & 31, warp = tid >> 5;
    const int lc8 = (lane & 7) * 8, rgrp = lane >> 3;
    __shared__ float skh[64], sqh[64];
    __shared__ float partq[8][64], partk[8][64];
    if (tid < 64) { skh[tid] = g_khsum[bh * 64 + tid] + EPS_; sqh[tid] = g_qhsum[bh * 64 + tid] + EPS_; }
    __syncthreads();
    float vkh[8], vqh[8];
    #pragma unroll
    for (int j = 0; j < 8; j++) { vkh[j] = skh[lc8 + j]; vqh[j] = sqh[lc8 + j]; }
    const size_t base = (size_t)bh * N_ * D_;

    uint4 rq[4], rk[4];
    #pragma unroll
    for (int it = 0; it < 4; it++) {
        const int n = rows0 + it * 32 + warp * 4 + rgrp;
        rq[it] = *(const uint4*)(g_qh + base + (size_t)n * D_ + lc8);
        rk[it] = *(const uint4*)(g_kh + base + (size_t)n * D_ + lc8);
    }
    float aq[8], ak[8];
    #pragma unroll
    for (int j = 0; j < 8; j++) { aq[j] = 0.f; ak[j] = 0.f; }
    #pragma unroll
    for (int it = 0; it < 4; it++) {
        const int n = rows0 + it * 32 + warp * 4 + rgrp;
        float q[8], k[8];
        h8_unpack(rq[it], q); h8_unpack(rk[it], k);
        float di = 0.f, dz = 0.f;
        #pragma unroll
        for (int j = 0; j < 8; j++) { di += (q[j] + EPS_) * vkh[j]; dz += (k[j] + EPS_) * vqh[j]; }
        #pragma unroll
        for (int o = 4; o; o >>= 1) {
            di += __shfl_xor_sync(0xffffffffu, di, o);
            dz += __shfl_xor_sync(0xffffffffu, dz, o);
        }
        const float si = 1.f / (di + EPS_), so = 1.f / (dz + EPS_);
        if ((lane & 7) == 0) g_si[bh * N_ + n] = si;
        #pragma unroll
        for (int j = 0; j < 8; j++) { aq[j] += q[j] * si; ak[j] += k[j] * so; }
    }
    #pragma unroll
    for (int j = 0; j < 8; j++) {
        aq[j] += __shfl_xor_sync(0xffffffffu, aq[j], 8);
        aq[j] += __shfl_xor_sync(0xffffffffu, aq[j], 16);
        ak[j] += __shfl_xor_sync(0xffffffffu, ak[j], 8);
        ak[j] += __shfl_xor_sync(0xffffffffu, ak[j], 16);
    }
    if (rgrp == 0) {
        #pragma unroll
        for (int j = 0; j < 8; j++) { partq[warp][lc8+j] = aq[j]; partk[warp][lc8+j] = ak[j]; }
    }
    __syncthreads();
    if (tid < 64) {
        float s = 0.f;
        #pragma unroll
        for (int w = 0; w < 8; w++) s += partq[w][tid];
        atomicAdd(&g_qsisum[bh * 64 + tid], s);
    } else if (tid < 128) {
        const int j = tid - 64;
        float s = 0.f;
        #pragma unroll
        for (int w = 0; w < 8; w++) s += partk[w][j];
        atomicAdd(&g_ksosum[bh * 64 + j], s);
    }
}

// ---------------- fused passF + kvagg ----------------
#define AGG_SPLIT 8
__global__ __launch_bounds__(256)
void passFG_kernel() {
    const int bh = blockIdx.x;
    const int rows0 = blockIdx.y * (N_ / AGG_SPLIT);
    const int tid = threadIdx.x, lane = tid & 31, warp = tid >> 5;
    const int tx = tid & 15, ty = tid >> 4;
    __shared__ float skso[64], sqsi[64];
    __shared__ __align__(16) float sk[16][64];
    __shared__ __align__(16) float sv[16][64];
    __shared__ float escs[16];
    if (tid < 64) { skso[tid] = g_ksosum[bh * 64 + tid] + EPS_; sqsi[tid] = g_qsisum[bh * 64 + tid] + EPS_; }
    __syncthreads();
    const float a0 = skso[lane*2], a1 = skso[lane*2+1];
    const float b0 = sqsi[lane*2], b1 = sqsi[lane*2+1];
    const size_t base = (size_t)bh * N_ * D_;
    float acc[4][4];
    #pragma unroll
    for (int i = 0; i < 4; i++)
        #pragma unroll
        for (int j = 0; j < 4; j++) acc[i][j] = 0.f;
    float sumexp_loc = 0.f;

    for (int c = 0; c < N_ / AGG_SPLIT; c += 16) {
        #pragma unroll
        for (int i = 0; i < 2; i++) {
            const int li = tid + i * 256;
            const int r = li >> 5, d2 = li & 31;
            const int n = rows0 + c + r;
            float2 fk = __half22float2(((const __half2*)(g_kh + base + (size_t)n * D_))[d2]);
            float2 fv = __half22float2(((const __half2*)(g_vh + base + (size_t)n * D_))[d2]);
            sk[r][d2*2] = fk.x; sk[r][d2*2+1] = fk.y;
            sv[r][d2*2] = fv.x; sv[r][d2*2+1] = fv.y;
        }
        __syncthreads();
        #pragma unroll
        for (int rr = 0; rr < 2; rr++) {
            const int r = warp * 2 + rr;
            const int n = rows0 + c + r;
            float2 q2 = __half22float2(*(const __half2*)(g_qh + base + (size_t)n * D_ + lane * 2));
            const float kx = sk[r][lane*2], ky = sk[r][lane*2+1];
            float dq = (q2.x + EPS_) * a0 + (q2.y + EPS_) * a1;
            float dk = (kx + EPS_) * b0 + (ky + EPS_) * b1;
            #pragma unroll
            for (int o = 16; o; o >>= 1) {
                dq += __shfl_xor_sync(0xffffffffu, dq, o);
                dk += __shfl_xor_sync(0xffffffffu, dk, o);
            }
            if (lane == 0) {
                const float csink = dq + EPS_;
                float cs = fminf(fmaxf(dk + EPS_, -1.f), 1.f);
                const float e = __expf(cs);
                escs[r] = e;
                sumexp_loc += e;
                const int idx = bh * N_ + n;
                g_ssink[idx] = g_si[idx] * sigm(csink);
            }
        }
        __syncthreads();
        #pragma unroll
        for (int r = 0; r < 16; r++) {
            const float es = escs[r];
            const float4 kk = ((const float4*)sk[r])[ty];
            float4 vv = ((const float4*)sv[r])[tx];
            vv.x *= es; vv.y *= es; vv.z *= es; vv.w *= es;
            acc[0][0] += kk.x*vv.x; acc[0][1] += kk.x*vv.y; acc[0][2] += kk.x*vv.z; acc[0][3] += kk.x*vv.w;
            acc[1][0] += kk.y*vv.x; acc[1][1] += kk.y*vv.y; acc[1][2] += kk.y*vv.z; acc[1][3] += kk.y*vv.w;
            acc[2][0] += kk.z*vv.x; acc[2][1] += kk.z*vv.y; acc[2][2] += kk.z*vv.z; acc[2][3] += kk.z*vv.w;
            acc[3][0] += kk.w*vv.x; acc[3][1] += kk.w*vv.y; acc[3][2] += kk.w*vv.z; acc[3][3] += kk.w*vv.w;
        }
        __syncthreads();
    }
    #pragma unroll
    for (int i = 0; i < 4; i++)
        #pragma unroll
        for (int j = 0; j < 4; j++)
            atomicAdd(&g_agg[bh * 4096 + (ty * 4 + i) * 64 + tx * 4 + j], acc[i][j]);
    if (lane == 0) atomicAdd(&g_sumexp[bh], sumexp_loc);
}

// ---------------- xout ----------------
__global__ __launch_bounds__(256)
void xout_kernel() {
    const int bh = blockIdx.x;
    const int b = bh / H_, h = bh % H_;
    const int rows0 = blockIdx.y * 64;
    const int tid = threadIdx.x;
    __shared__ __align__(16) float sagg[64][64];
    __shared__ __align__(16) float sq[64][65];
    const float scl = (float)N_ / g_sumexp[bh];
    #pragma unroll
    for (int i = 0; i < 16; i++) {
        const int li = tid + i * 256;
        sagg[li >> 6][li & 63] = g_agg[bh * 4096 + li];
    }
    const size_t base = (size_t)bh * N_ * D_ + (size_t)rows0 * D_;
    #pragma unroll
    for (int i = 0; i < 8; i++) {
        const int li = tid + i * 256;
        const int r = li >> 5, d2 = li & 31;
        float2 f = __half22float2(((const __half2*)(g_qh + base + (size_t)r * D_))[d2]);
        sq[r][d2*2] = f.x; sq[r][d2*2+1] = f.y;
    }
    __syncthreads();
    const int r = tid >> 2, ch = tid & 3;
    float acc[16];
    #pragma unroll
    for (int j = 0; j < 16; j++) acc[j] = 0.f;
    #pragma unroll 8
    for (int d = 0; d < 64; d++) {
        const float qv = sq[r][d];
        const float4* ag = (const float4*)(&sagg[d][ch * 16]);
        #pragma unroll
        for (int j4 = 0; j4 < 4; j4++) {
            float4 av = ag[j4];
            acc[j4*4+0] += qv * av.x; acc[j4*4+1] += qv * av.y;
            acc[j4*4+2] += qv * av.z; acc[j4*4+3] += qv * av.w;
        }
    }
    const int n = rows0 + r;
    const float s = g_ssink[bh * N_ + n] * scl;
    __half* xr = g_ah + ((size_t)b * N_ + n) * C_ + h * 64 + ch * 16;
    uint32_t u[8];
    #pragma unroll
    for (int j = 0; j < 8; j++) {
        __half2 hh = __floats2half2_rn(acc[2*j] * s, acc[2*j+1] * s);
        u[j] = *(uint32_t*)&hh;
    }
    ((uint4*)xr)[0] = make_uint4(u[0], u[1], u[2], u[3]);
    ((uint4*)xr)[1] = make_uint4(u[4], u[5], u[6], u[7]);
}

// ---------------- launch ----------------
extern "C" void kernel_launch(void* const* d_in, const int* in_sizes, int n_in,
                              void* d_out, int out_size) {
    const float* q      = (const float*)d_in[0];
    const float* kv     = (const float*)d_in[1];
    const float* motion = (const float*)d_in[2];
    const float* Wq = (const float*)d_in[3];  const float* bq = (const float*)d_in[4];
    const float* Wk = (const float*)d_in[5];  const float* bk = (const float*)d_in[6];
    const float* Wv = (const float*)d_in[7];  const float* bv = (const float*)d_in[8];
    const float* Wm = (const float*)d_in[9];  const float* bm = (const float*)d_in[10];
    const float* Wo = (const float*)d_in[11]; const float* bo = (const float*)d_in[12];
    float* out = (float*)d_out;

    __half *p_qh, *p_kh, *p_vh, *p_mh, *p_ah, *p_wh;
    cudaGetSymbolAddress((void**)&p_qh, g_qh);
    cudaGetSymbolAddress((void**)&p_kh, g_kh);
    cudaGetSymbolAddress((void**)&p_vh, g_vh);
    cudaGetSymbolAddress((void**)&p_mh, g_mh);
    cudaGetSymbolAddress((void**)&p_ah, g_ah);
    cudaGetSymbolAddress((void**)&p_wh, g_wh);

    cudaFuncSetAttribute(gemm_proj, cudaFuncAttributeMaxDynamicSharedMemorySize, GEMM_SMEM);
    cudaFuncSetAttribute(gemm_out,  cudaFuncAttributeMaxDynamicSharedMemorySize, GEMM_SMEM);

    const dim3 gProj(C_ / 128, M_ / 128, 4);
    const dim3 gOut(C_ / 128, M_ / 128);
    const dim3 gRed(BH_, SPLIT_);
    const int actN4 = M_ * C_ / 4;
    const int wN4   = C_ * C_ / 4;
    const int actBlk = (actN4 + 255) / 256;
    const int wBlk   = (wN4 + 255) / 256;
    const size_t WS = (size_t)C_ * C_;

    zero_kernel<<<(BH_*D_*D_ + 255) / 256, 256>>>();
    f2h_w5_kernel<<<dim3(wBlk, 5), 256>>>(Wq, Wk, Wv, Wm, Wo, p_wh);
    f2h_acts_kernel<<<dim3(actBlk, 3), 256>>>(q, kv, motion, p_ah);

    gemm_proj<<<gProj, 256, GEMM_SMEM>>>(p_ah, p_wh, bq, bk, bv, bm, p_qh, p_kh, p_vh, p_mh);

    passBB_kernel<<<gRed, 256>>>();
    passC_kernel<<<gRed, 256>>>();
    passE_kernel<<<gRed, 256>>>();
    passFG_kernel<<<dim3(BH_, AGG_SPLIT), 256>>>();
    xout_kernel<<<dim3(BH_, N_ / 64), 256>>>();

    gemm_out<<<gOut, 256, GEMM_SMEM>>>(p_ah, p_wh + 4*WS, bo, out);
}